// round 10
// baseline (speedup 1.0000x reference)
#include <cuda_runtime.h>
#include <math.h>
#include <stdint.h>

#define N 256
#define C 128
#define H 4
#define D 32
#define NP (N*N)            // 65536 positions
#define EPSV 1e-5f
#define INFV 1000000000.0f
#define QT 64               // attention query tile

// Scratch (static device arrays; no allocation in kernel_launch)
__device__ float g_xn[NP*C];        // layernormed x           32 MB
__device__ float g_tri[H*N*N];      // tri bias [h][q][k]       1 MB
__device__ float g_gate[NP*C];      // gate logits             32 MB
__device__ float g_o[NP*C];         // attention output        32 MB

// round fp32 -> tf32 bit pattern (rna), returned as float bits
__device__ __forceinline__ float tf32r(float x) {
    uint32_t u;
    asm("cvt.rna.tf32.f32 %0, %1;" : "=r"(u) : "f"(x));
    return __uint_as_float(u);
}

__device__ __forceinline__ void mma_tf32(float& d0, float& d1, float& d2, float& d3,
                                         uint32_t a0, uint32_t a1, uint32_t a2, uint32_t a3,
                                         uint32_t b0, uint32_t b1) {
    asm volatile(
        "mma.sync.aligned.m16n8k8.row.col.f32.tf32.tf32.f32 "
        "{%0,%1,%2,%3}, {%4,%5,%6,%7}, {%8,%9}, {%0,%1,%2,%3};\n"
        : "+f"(d0), "+f"(d1), "+f"(d2), "+f"(d3)
        : "r"(a0), "r"(a1), "r"(a2), "r"(a3), "r"(b0), "r"(b1));
}

// ---------------------------------------------------------------------------
// Kernel 1: LayerNorm over C + triangle-bias projection ([h][q][k] layout)
// ---------------------------------------------------------------------------
__global__ void k_ln_tri(const float* __restrict__ x,
                         const float* __restrict__ ln_w,
                         const float* __restrict__ ln_b,
                         const float* __restrict__ w_tri) {
    __shared__ float swt[H*C];
    int tid = threadIdx.x;
    swt[tid]       = w_tri[tid];
    swt[tid + 256] = w_tri[tid + 256];
    __syncthreads();

    int warp = tid >> 5, lane = tid & 31;
    int pos = (blockIdx.x << 3) + warp;

    const float4 a = ((const float4*)(x + (size_t)pos * C))[lane];
    float s  = a.x + a.y + a.z + a.w;
    float s2 = a.x*a.x + a.y*a.y + a.z*a.z + a.w*a.w;
#pragma unroll
    for (int o = 16; o > 0; o >>= 1) {
        s  += __shfl_xor_sync(0xffffffffu, s,  o);
        s2 += __shfl_xor_sync(0xffffffffu, s2, o);
    }
    float mu   = s * (1.0f / C);
    float var  = s2 * (1.0f / C) - mu * mu;
    float rstd = rsqrtf(var + EPSV);

    float4 w = ((const float4*)ln_w)[lane];
    float4 b = ((const float4*)ln_b)[lane];
    float4 xn;
    xn.x = (a.x - mu) * rstd * w.x + b.x;
    xn.y = (a.y - mu) * rstd * w.y + b.y;
    xn.z = (a.z - mu) * rstd * w.z + b.z;
    xn.w = (a.w - mu) * rstd * w.w + b.w;
    ((float4*)(g_xn + (size_t)pos * C))[lane] = xn;

    float t[H];
#pragma unroll
    for (int h = 0; h < H; ++h) {
        const float4 wt = ((const float4*)(swt + h * C))[lane];
        t[h] = xn.x*wt.x + xn.y*wt.y + xn.z*wt.z + xn.w*wt.w;
    }
#pragma unroll
    for (int h = 0; h < H; ++h)
#pragma unroll
        for (int o = 16; o > 0; o >>= 1)
            t[h] += __shfl_xor_sync(0xffffffffu, t[h], o);

    if (lane == 0) {
        int q = pos >> 8, k = pos & 255;
#pragma unroll
        for (int h = 0; h < H; ++h)
            g_tri[(h * N + q) * N + k] = t[h];   // [h][q][k]
    }
}

struct MmaAcc { float d[2][8][4]; };   // [mt][nt][reg]

// M-side streamed chunk (pitch 36), N-side resident (pitch 132, cbase offset)
__device__ __forceinline__ void mma_chunk_mres(const float (*Ac)[36], const float (*Br)[132],
                                               int cbase, int wm, int wn, int g, int tq,
                                               MmaAcc& A) {
#pragma unroll
    for (int ks = 0; ks < 32; ks += 8) {
        uint32_t af[2][4];
#pragma unroll
        for (int mt = 0; mt < 2; ++mt) {
            int r = wm * 32 + mt * 16;
            af[mt][0] = __float_as_uint(Ac[r + g][ks + tq]);
            af[mt][1] = __float_as_uint(Ac[r + g + 8][ks + tq]);
            af[mt][2] = __float_as_uint(Ac[r + g][ks + tq + 4]);
            af[mt][3] = __float_as_uint(Ac[r + g + 8][ks + tq + 4]);
        }
#pragma unroll
        for (int nt = 0; nt < 8; ++nt) {
            int cb = wn * 64 + nt * 8;
            uint32_t b0 = __float_as_uint(Br[cb + g][cbase + ks + tq]);
            uint32_t b1 = __float_as_uint(Br[cb + g][cbase + ks + tq + 4]);
#pragma unroll
            for (int mt = 0; mt < 2; ++mt)
                mma_tf32(A.d[mt][nt][0], A.d[mt][nt][1], A.d[mt][nt][2], A.d[mt][nt][3],
                         af[mt][0], af[mt][1], af[mt][2], af[mt][3], b0, b1);
        }
    }
}

// M-side resident (pitch 132, cbase), N-side streamed chunk (pitch 36)
__device__ __forceinline__ void mma_chunk_nstr(const float (*Ar)[132], const float (*Bc)[36],
                                               int cbase, int wm, int wn, int g, int tq,
                                               MmaAcc& A) {
#pragma unroll
    for (int ks = 0; ks < 32; ks += 8) {
        uint32_t af[2][4];
#pragma unroll
        for (int mt = 0; mt < 2; ++mt) {
            int r = wm * 32 + mt * 16;
            af[mt][0] = __float_as_uint(Ar[r + g][cbase + ks + tq]);
            af[mt][1] = __float_as_uint(Ar[r + g + 8][cbase + ks + tq]);
            af[mt][2] = __float_as_uint(Ar[r + g][cbase + ks + tq + 4]);
            af[mt][3] = __float_as_uint(Ar[r + g + 8][cbase + ks + tq + 4]);
        }
#pragma unroll
        for (int nt = 0; nt < 8; ++nt) {
            int cb = wn * 64 + nt * 8;
            uint32_t b0 = __float_as_uint(Bc[cb + g][ks + tq]);
            uint32_t b1 = __float_as_uint(Bc[cb + g][ks + tq + 4]);
#pragma unroll
            for (int mt = 0; mt < 2; ++mt)
                mma_tf32(A.d[mt][nt][0], A.d[mt][nt][1], A.d[mt][nt][2], A.d[mt][nt][3],
                         af[mt][0], af[mt][1], af[mt][2], af[mt][3], b0, b1);
        }
    }
}

// ---------------------------------------------------------------------------
// Kernel 2: gate-logit projection only. grid = NP/128.
// ---------------------------------------------------------------------------
struct ProjSmem {
    float As[128][132];     // resident xn tile   67584 B
    float Bs[2][128][36];   // weight chunks      36864 B
};                          // 104448 B

__global__ void __launch_bounds__(256, 2)
k_gate(const float* __restrict__ wg) {
    extern __shared__ char smraw[];
    ProjSmem* sm = (ProjSmem*)smraw;
    int tid = threadIdx.x;
    int m0 = blockIdx.x * 128;
    int w = tid >> 5, lane = tid & 31;
    int wm = w >> 1, wn = w & 1;
    int g = lane >> 2, tq = lane & 3;

#pragma unroll
    for (int t = 0; t < 16; ++t) {
        int idx = tid + t * 256;          // 0..4095
        int row = idx >> 5, j4 = idx & 31;
        float4 a = *(const float4*)&g_xn[(size_t)(m0 + row) * C + j4 * 4];
        float4 r = {tf32r(a.x), tf32r(a.y), tf32r(a.z), tf32r(a.w)};
        *(float4*)&sm->As[row][j4 * 4] = r;
    }
#pragma unroll
    for (int t = 0; t < 4; ++t) {
        int idx = tid + t * 256;          // 0..1023
        int row = idx >> 3, j = idx & 7;
        float4 b = *(const float4*)&wg[(size_t)row * C + j * 4];
        float4 r = {tf32r(b.x), tf32r(b.y), tf32r(b.z), tf32r(b.w)};
        *(float4*)&sm->Bs[0][row][j * 4] = r;
    }
    __syncthreads();

    MmaAcc acc;
#pragma unroll
    for (int mt = 0; mt < 2; ++mt)
#pragma unroll
        for (int nt = 0; nt < 8; ++nt)
#pragma unroll
            for (int r = 0; r < 4; ++r) acc.d[mt][nt][r] = 0.0f;

    for (int kc = 0; kc < 4; ++kc) {
        float4 pre[4];
        if (kc < 3) {
#pragma unroll
            for (int t = 0; t < 4; ++t) {
                int idx = tid + t * 256;
                int row = idx >> 3, j = idx & 7;
                pre[t] = *(const float4*)&wg[(size_t)row * C + (kc + 1) * 32 + j * 4];
            }
        }
        mma_chunk_nstr(sm->As, sm->Bs[kc & 1], kc * 32, wm, wn, g, tq, acc);
        if (kc < 3) {
#pragma unroll
            for (int t = 0; t < 4; ++t) {
                int idx = tid + t * 256;
                int row = idx >> 3, j = idx & 7;
                float4 r = {tf32r(pre[t].x), tf32r(pre[t].y), tf32r(pre[t].z), tf32r(pre[t].w)};
                *(float4*)&sm->Bs[(kc + 1) & 1][row][j * 4] = r;
            }
            __syncthreads();
        }
    }

#pragma unroll
    for (int mt = 0; mt < 2; ++mt) {
        int r0 = m0 + wm * 32 + mt * 16 + g;
#pragma unroll
        for (int nt = 0; nt < 8; ++nt) {
            int cb = wn * 64 + nt * 8 + 2 * tq;
            *(float2*)&g_gate[(size_t)r0 * C + cb] =
                make_float2(acc.d[mt][nt][0], acc.d[mt][nt][1]);
            *(float2*)&g_gate[(size_t)(r0 + 8) * C + cb] =
                make_float2(acc.d[mt][nt][2], acc.d[mt][nt][3]);
        }
    }
}

// ---------------------------------------------------------------------------
// Kernel 3: fused projection + MMA attention. Block = (i, h), 512 threads.
// Phase 1: K/V/Q = xn[i] x {Wk,Wv,Wq}_h via MMA (register-prefetched chunks).
// Phase 2: per 64-query tile: S = Q K^T + tri + mask; softmax; O = P V
//          (tri tile for qt+1 register-prefetched during PV).
// Warp grid 4(M) x 4(N).
// ---------------------------------------------------------------------------
struct AttnSmem {
    union {
        struct {
            float W3[96][132];   // stacked [k|v|q] head weights  50688 B
            float Xs[64][132];   // xn chunk                      33792 B
        } p;
        float T[QT][260];        // tri bias -> P                 66560 B
    } u;                         // 84480 B
    float Ks[256][36];           // 36864 B
    float Vs[256][36];           // 36864 B
    float Qs[256][36];           // 36864 B (pre-scaled)
    float mb[256];               //  1024 B
    float rmax[QT][4];           //  1024 B
    float rsum[QT][4];           //  1024 B
};                               // 198144 B

__global__ void __launch_bounds__(512)
k_attn(const float* __restrict__ mask,
       const float* __restrict__ wq, const float* __restrict__ wk,
       const float* __restrict__ wv) {
    extern __shared__ char smraw[];
    AttnSmem* sm = (AttnSmem*)smraw;

    int i = blockIdx.x, h = blockIdx.y;
    int tid = threadIdx.x, w = tid >> 5, lane = tid & 31;
    int g = lane >> 2, tq = lane & 3;
    int wm = w >> 2, wn = w & 3;          // 4 warps along M, 4 along N
    const float sc = 0.17677669529663688f;  // 1/sqrt(32)

    // ===================== Phase 1: project K/V/Q =====================
    // head weights stacked: rows 0-31 = Wk_h, 32-63 = Wv_h, 64-95 = Wq_h
#pragma unroll
    for (int t = 0; t < 6; ++t) {
        int idx = tid + t * 512;          // 0..3071
        int row = idx >> 5, j4 = idx & 31;
        const float* src = (row < 32) ? wk : (row < 64) ? wv : wq;
        float4 b = *(const float4*)&src[(size_t)(h * 32 + (row & 31)) * C + j4 * 4];
        float4 r = {tf32r(b.x), tf32r(b.y), tf32r(b.z), tf32r(b.w)};
        *(float4*)&sm->u.p.W3[row][j4 * 4] = r;
    }
    if (tid < 256) sm->mb[tid] = INFV * (mask[i * N + tid] - 1.0f);

    // stage xn chunk 0
    float4 xpre[4];
#pragma unroll
    for (int t = 0; t < 4; ++t) {
        int idx = tid + t * 512;          // 0..2047
        int row = idx >> 5, j4 = idx & 31;
        xpre[t] = *(const float4*)&g_xn[((size_t)(i * N + row)) * C + j4 * 4];
    }
#pragma unroll
    for (int t = 0; t < 4; ++t) {
        int idx = tid + t * 512;
        int row = idx >> 5, j4 = idx & 31;
        float4 r = {tf32r(xpre[t].x), tf32r(xpre[t].y), tf32r(xpre[t].z), tf32r(xpre[t].w)};
        *(float4*)&sm->u.p.Xs[row][j4 * 4] = r;
    }
    __syncthreads();

    for (int c = 0; c < 4; ++c) {
        // prefetch next chunk while doing MMAs
        if (c < 3) {
#pragma unroll
            for (int t = 0; t < 4; ++t) {
                int idx = tid + t * 512;
                int row = idx >> 5, j4 = idx & 31;
                xpre[t] = *(const float4*)&g_xn[((size_t)(i * N + (c + 1) * 64 + row)) * C + j4 * 4];
            }
        }
        // GEMM: M=64 (xn rows), N=96 (kvq dims), K=128. Warp tile 16x24.
        float pacc[3][4] = {};
#pragma unroll
        for (int ks = 0; ks < 128; ks += 8) {
            int r = wm * 16;
            uint32_t a0 = __float_as_uint(sm->u.p.Xs[r + g][ks + tq]);
            uint32_t a1 = __float_as_uint(sm->u.p.Xs[r + g + 8][ks + tq]);
            uint32_t a2 = __float_as_uint(sm->u.p.Xs[r + g][ks + tq + 4]);
            uint32_t a3 = __float_as_uint(sm->u.p.Xs[r + g + 8][ks + tq + 4]);
#pragma unroll
            for (int nt = 0; nt < 3; ++nt) {
                int cb = wn * 24 + nt * 8;
                uint32_t b0 = __float_as_uint(sm->u.p.W3[cb + g][ks + tq]);
                uint32_t b1 = __float_as_uint(sm->u.p.W3[cb + g][ks + tq + 4]);
                mma_tf32(pacc[nt][0], pacc[nt][1], pacc[nt][2], pacc[nt][3],
                         a0, a1, a2, a3, b0, b1);
            }
        }
        // scatter results into Ks / Vs / Qs (Q pre-scaled)
        {
            int row0 = c * 64 + wm * 16 + g;
#pragma unroll
            for (int nt = 0; nt < 3; ++nt) {
                int col = wn * 24 + nt * 8 + 2 * tq;
                int sel = col >> 5, off = col & 31;
                float m0 = pacc[nt][0], m1 = pacc[nt][1];
                float m2 = pacc[nt][2], m3 = pacc[nt][3];
                if (sel == 2) { m0 *= sc; m1 *= sc; m2 *= sc; m3 *= sc; }
                float* dst = (sel == 0) ? &sm->Ks[0][0] :
                             (sel == 1) ? &sm->Vs[0][0] : &sm->Qs[0][0];
                dst[row0 * 36 + off]           = tf32r(m0);
                dst[row0 * 36 + off + 1]       = tf32r(m1);
                dst[(row0 + 8) * 36 + off]     = tf32r(m2);
                dst[(row0 + 8) * 36 + off + 1] = tf32r(m3);
            }
        }
        if (c < 3) {
            __syncthreads();   // all MMA reads of Xs done
#pragma unroll
            for (int t = 0; t < 4; ++t) {
                int idx = tid + t * 512;
                int row = idx >> 5, j4 = idx & 31;
                float4 r = {tf32r(xpre[t].x), tf32r(xpre[t].y), tf32r(xpre[t].z), tf32r(xpre[t].w)};
                *(float4*)&sm->u.p.Xs[row][j4 * 4] = r;
            }
            __syncthreads();
        }
    }
    __syncthreads();   // phase1 done; union region free; K/V/Q visible

    // stage tri(qt=0) into T
#pragma unroll
    for (int t = 0; t < 8; ++t) {
        int idx = tid + t * 512;          // 0..4095
        int row = idx >> 6, k4 = idx & 63;
        float4 tv = *(const float4*)&g_tri[((size_t)(h * N + row)) * N + k4 * 4];
        *(float4*)&sm->u.T[row][k4 * 4] = tv;
    }
    __syncthreads();

    // ===================== Phase 2: attention =====================
    for (int qt = 0; qt < 4; ++qt) {
        int q0 = qt * QT;

        // ---- S = Q K^T : warp tile 16x64, 8nt, k=32 ----
        float sacc[8][4];
#pragma unroll
        for (int nt = 0; nt < 8; ++nt)
#pragma unroll
            for (int r = 0; r < 4; ++r) sacc[nt][r] = 0.0f;

#pragma unroll
        for (int ks = 0; ks < 32; ks += 8) {
            int r = q0 + wm * 16;
            uint32_t a0 = __float_as_uint(sm->Qs[r + g][ks + tq]);
            uint32_t a1 = __float_as_uint(sm->Qs[r + g + 8][ks + tq]);
            uint32_t a2 = __float_as_uint(sm->Qs[r + g][ks + tq + 4]);
            uint32_t a3 = __float_as_uint(sm->Qs[r + g + 8][ks + tq + 4]);
#pragma unroll
            for (int nt = 0; nt < 8; ++nt) {
                int cb = wn * 64 + nt * 8;
                uint32_t b0 = __float_as_uint(sm->Ks[cb + g][ks + tq]);
                uint32_t b1 = __float_as_uint(sm->Ks[cb + g][ks + tq + 4]);
                mma_tf32(sacc[nt][0], sacc[nt][1], sacc[nt][2], sacc[nt][3],
                         a0, a1, a2, a3, b0, b1);
            }
        }

        // ---- add tri + mask bias; partial row max ----
        int r0 = wm * 16 + g;
        float pmax0 = -3.4e38f, pmax1 = -3.4e38f;
#pragma unroll
        for (int nt = 0; nt < 8; ++nt) {
            int c0 = wn * 64 + nt * 8 + 2 * tq;
            float m0v = sm->mb[c0], m1v = sm->mb[c0 + 1];
            sacc[nt][0] += sm->u.T[r0][c0]     + m0v;
            sacc[nt][1] += sm->u.T[r0][c0 + 1] + m1v;
            sacc[nt][2] += sm->u.T[r0 + 8][c0]     + m0v;
            sacc[nt][3] += sm->u.T[r0 + 8][c0 + 1] + m1v;
            pmax0 = fmaxf(pmax0, fmaxf(sacc[nt][0], sacc[nt][1]));
            pmax1 = fmaxf(pmax1, fmaxf(sacc[nt][2], sacc[nt][3]));
        }
        pmax0 = fmaxf(pmax0, __shfl_xor_sync(0xffffffffu, pmax0, 1));
        pmax0 = fmaxf(pmax0, __shfl_xor_sync(0xffffffffu, pmax0, 2));
        pmax1 = fmaxf(pmax1, __shfl_xor_sync(0xffffffffu, pmax1, 1));
        pmax1 = fmaxf(pmax1, __shfl_xor_sync(0xffffffffu, pmax1, 2));
        if (tq == 0) {
            sm->rmax[r0][wn]     = pmax0;
            sm->rmax[r0 + 8][wn] = pmax1;
        }
        __syncthreads();

        // ---- exp + write P (tf32-rounded) + partial row sums ----
        float4 m4a = *(float4*)sm->rmax[r0];
        float rm0 = fmaxf(fmaxf(m4a.x, m4a.y), fmaxf(m4a.z, m4a.w));
        float4 m4b = *(float4*)sm->rmax[r0 + 8];
        float rm1 = fmaxf(fmaxf(m4b.x, m4b.y), fmaxf(m4b.z, m4b.w));
        float psum0 = 0.0f, psum1 = 0.0f;
#pragma unroll
        for (int nt = 0; nt < 8; ++nt) {
            int c0 = wn * 64 + nt * 8 + 2 * tq;
            float p0 = tf32r(__expf(sacc[nt][0] - rm0));
            float p1 = tf32r(__expf(sacc[nt][1] - rm0));
            float p2 = tf32r(__expf(sacc[nt][2] - rm1));
            float p3 = tf32r(__expf(sacc[nt][3] - rm1));
            psum0 += p0 + p1;
            psum1 += p2 + p3;
            sm->u.T[r0][c0] = p0;     sm->u.T[r0][c0 + 1] = p1;
            sm->u.T[r0 + 8][c0] = p2; sm->u.T[r0 + 8][c0 + 1] = p3;
        }
        psum0 += __shfl_xor_sync(0xffffffffu, psum0, 1);
        psum0 += __shfl_xor_sync(0xffffffffu, psum0, 2);
        psum1 += __shfl_xor_sync(0xffffffffu, psum1, 1);
        psum1 += __shfl_xor_sync(0xffffffffu, psum1, 2);
        if (tq == 0) {
            sm->rsum[r0][wn]     = psum0;
            sm->rsum[r0 + 8][wn] = psum1;
        }
        __syncthreads();

        // ---- prefetch tri(qt+1) into registers (overlaps PV) ----
        float4 tpre[8];
        if (qt < 3) {
#pragma unroll
            for (int t = 0; t < 8; ++t) {
                int idx = tid + t * 512;
                int row = idx >> 6, k4 = idx & 63;
                tpre[t] = *(const float4*)&g_tri[((size_t)(h * N + q0 + 64 + row)) * N + k4 * 4];
            }
        }

        // ---- O = P V : warp tile 16x8, k=256 ----
        int nb = wn * 8;
        float oacc[4] = {0, 0, 0, 0};
#pragma unroll
        for (int ks8 = 0; ks8 < 32; ++ks8) {
            int kk = ks8 * 8;
            uint32_t b0 = __float_as_uint(sm->Vs[kk + tq][nb + g]);
            uint32_t b1 = __float_as_uint(sm->Vs[kk + tq + 4][nb + g]);
            uint32_t a0 = __float_as_uint(sm->u.T[r0][kk + tq]);
            uint32_t a1 = __float_as_uint(sm->u.T[r0 + 8][kk + tq]);
            uint32_t a2 = __float_as_uint(sm->u.T[r0][kk + tq + 4]);
            uint32_t a3 = __float_as_uint(sm->u.T[r0 + 8][kk + tq + 4]);
            mma_tf32(oacc[0], oacc[1], oacc[2], oacc[3], a0, a1, a2, a3, b0, b1);
        }

        // ---- epilogue: normalize by row sums, store ----
        {
            float4 s0 = *(float4*)sm->rsum[r0];
            float inv0 = 1.0f / (s0.x + s0.y + s0.z + s0.w);
            float4 s1 = *(float4*)sm->rsum[r0 + 8];
            float inv1 = 1.0f / (s1.x + s1.y + s1.z + s1.w);
            int col = nb + 2 * tq;
            size_t b0a = ((size_t)(i * N + q0 + r0)) * C + h * D + col;
            *(float2*)&g_o[b0a] = make_float2(oacc[0] * inv0, oacc[1] * inv0);
            size_t b1a = ((size_t)(i * N + q0 + r0 + 8)) * C + h * D + col;
            *(float2*)&g_o[b1a] = make_float2(oacc[2] * inv1, oacc[3] * inv1);
        }

        if (qt < 3) {
            __syncthreads();   // all PV reads of T done
#pragma unroll
            for (int t = 0; t < 8; ++t) {
                int idx = tid + t * 512;
                int row = idx >> 6, k4 = idx & 63;
                *(float4*)&sm->u.T[row][k4 * 4] = tpre[t];
            }
            __syncthreads();   // tri(qt+1) visible
        }
    }
}

// ---------------------------------------------------------------------------
// Kernel 4: gated output projection. grid=NP/128.
// B (wo) resident; A (gated o) streamed with register prefetch.
// ---------------------------------------------------------------------------
struct OutSmem {
    float Bs[128][132];     // resident wo        67584 B
    float As[2][128][36];   // gated A chunks     36864 B
};                          // 104448 B

__global__ void __launch_bounds__(256)
k_out(const float* __restrict__ wo, const float* __restrict__ bg,
      const float* __restrict__ bo, float* __restrict__ out) {
    extern __shared__ char smraw[];
    OutSmem* sm = (OutSmem*)smraw;
    int tid = threadIdx.x;
    int m0 = blockIdx.x * 128;
    int w = tid >> 5, lane = tid & 31;
    int wm = w >> 1, wn = w & 1;
    int g = lane >> 2, tq = lane & 3;

#pragma unroll
    for (int t = 0; t < 16; ++t) {
        int idx = tid + t * 256;
        int row = idx >> 5, j4 = idx & 31;
        float4 b = *(const float4*)&wo[(size_t)row * C + j4 * 4];
        float4 r = {tf32r(b.x), tf32r(b.y), tf32r(b.z), tf32r(b.w)};
        *(float4*)&sm->Bs[row][j4 * 4] = r;
    }
#pragma unroll
    for (int t = 0; t < 4; ++t) {
        int idx = tid + t * 256;
        int row = idx >> 3, j = idx & 7;
        int col = j * 4;
        size_t ai = (size_t)(m0 + row) * C + col;
        float4 ov = *(const float4*)&g_o[ai];
        float4 gp = *(const float4*)&g_gate[ai];
        float4 bgv = *(const float4*)&bg[col];
        float4 r;
        r.x = tf32r(ov.x / (1.0f + __expf(-(gp.x + bgv.x))));
        r.y = tf32r(ov.y / (1.0f + __expf(-(gp.y + bgv.y))));
        r.z = tf32r(ov.z / (1.0f + __expf(-(gp.z + bgv.z))));
        r.w = tf32r(ov.w / (1.0f + __expf(-(gp.w + bgv.w))));
        *(float4*)&sm->As[0][row][j * 4] = r;
    }
    __syncthreads();

    MmaAcc acc;
#pragma unroll
    for (int mt = 0; mt < 2; ++mt)
#pragma unroll
        for (int nt = 0; nt < 8; ++nt)
#pragma unroll
            for (int r = 0; r < 4; ++r) acc.d[mt][nt][r] = 0.0f;

    for (int kc = 0; kc < 4; ++kc) {
        float4 po[4], pg[4];
        if (kc < 3) {
#pragma unroll
            for (int t = 0; t < 4; ++t) {
                int idx = tid + t * 256;
                int row = idx >> 3, j = idx & 7;
                size_t ai = (size_t)(m0 + row) * C + (kc + 1) * 32 + j * 4;
                po[t] = *(const float4*)&g_o[ai];
                pg[t] = *(const float4*)&g_gate[ai];
            }
        }
        mma_chunk_mres(sm->As[kc & 1], sm->Bs, kc * 32, wm, wn, g, tq, acc);
        if (kc < 3) {
#pragma unroll
            for (int t = 0; t < 4; ++t) {
                int idx = tid + t * 256;
                int row = idx >> 3, j = idx & 7;
                int col = (kc + 1) * 32 + j * 4;
                float4 bgv = *(const float4*)&bg[col];
                float4 r;
                r.x = tf32r(po[t].x / (1.0f + __expf(-(pg[t].x + bgv.x))));
                r.y = tf32r(po[t].y / (1.0f + __expf(-(pg[t].y + bgv.y))));
                r.z = tf32r(po[t].z / (1.0f + __expf(-(pg[t].z + bgv.z))));
                r.w = tf32r(po[t].w / (1.0f + __expf(-(pg[t].w + bgv.w))));
                *(float4*)&sm->As[(kc + 1) & 1][row][j * 4] = r;
            }
            __syncthreads();
        }
    }

#pragma unroll
    for (int mt = 0; mt < 2; ++mt) {
        int r0 = m0 + wm * 32 + mt * 16 + g;
#pragma unroll
        for (int nt = 0; nt < 8; ++nt) {
            int cb = wn * 64 + nt * 8 + 2 * tq;
            float2 bov = *(const float2*)&bo[cb];
            *(float2*)&out[(size_t)r0 * C + cb] =
                make_float2(acc.d[mt][nt][0] + bov.x, acc.d[mt][nt][1] + bov.y);
            *(float2*)&out[(size_t)(r0 + 8) * C + cb] =
                make_float2(acc.d[mt][nt][2] + bov.x, acc.d[mt][nt][3] + bov.y);
        }
    }
}

// ---------------------------------------------------------------------------
extern "C" void kernel_launch(void* const* d_in, const int* in_sizes, int n_in,
                              void* d_out, int out_size) {
    const float* x     = (const float*)d_in[0];
    const float* mask  = (const float*)d_in[1];
    const float* ln_w  = (const float*)d_in[2];
    const float* ln_b  = (const float*)d_in[3];
    const float* w_tri = (const float*)d_in[4];
    const float* wq    = (const float*)d_in[5];
    const float* wk    = (const float*)d_in[6];
    const float* wv    = (const float*)d_in[7];
    const float* wg    = (const float*)d_in[8];
    const float* bg    = (const float*)d_in[9];
    const float* wo    = (const float*)d_in[10];
    const float* bo    = (const float*)d_in[11];
    float* out = (float*)d_out;

    (void)in_sizes; (void)n_in; (void)out_size;

    cudaFuncSetAttribute(k_gate, cudaFuncAttributeMaxDynamicSharedMemorySize,
                         (int)sizeof(ProjSmem));
    cudaFuncSetAttribute(k_out, cudaFuncAttributeMaxDynamicSharedMemorySize,
                         (int)sizeof(OutSmem));
    cudaFuncSetAttribute(k_attn, cudaFuncAttributeMaxDynamicSharedMemorySize,
                         (int)sizeof(AttnSmem));

    k_ln_tri<<<NP / 8, 256>>>(x, ln_w, ln_b, w_tri);
    k_gate<<<NP / 128, 256, sizeof(ProjSmem)>>>(wg);
    k_attn<<<dim3(N, H), 512, sizeof(AttnSmem)>>>(mask, wq, wk, wv);
    k_out<<<NP / 128, 256, sizeof(OutSmem)>>>(wo, bg, bo, out);
}

// round 11
// speedup vs baseline: 1.0450x; 1.0450x over previous
#include <cuda_runtime.h>
#include <math.h>
#include <stdint.h>

#define N 256
#define C 128
#define H 4
#define D 32
#define NP (N*N)            // 65536 positions
#define EPSV 1e-5f
#define INFV 1000000000.0f
#define QT 64               // attention query tile

// Scratch (static device arrays; no allocation in kernel_launch)
__device__ float g_xn[NP*C];        // layernormed x           32 MB
__device__ float g_tri[H*N*N];      // tri bias [h][q][k]       1 MB
__device__ float g_o[NP*C];         // gated attention output  32 MB

// round fp32 -> tf32 bit pattern (rna), returned as float bits
__device__ __forceinline__ float tf32r(float x) {
    uint32_t u;
    asm("cvt.rna.tf32.f32 %0, %1;" : "=r"(u) : "f"(x));
    return __uint_as_float(u);
}

__device__ __forceinline__ void mma_tf32(float& d0, float& d1, float& d2, float& d3,
                                         uint32_t a0, uint32_t a1, uint32_t a2, uint32_t a3,
                                         uint32_t b0, uint32_t b1) {
    asm volatile(
        "mma.sync.aligned.m16n8k8.row.col.f32.tf32.tf32.f32 "
        "{%0,%1,%2,%3}, {%4,%5,%6,%7}, {%8,%9}, {%0,%1,%2,%3};\n"
        : "+f"(d0), "+f"(d1), "+f"(d2), "+f"(d3)
        : "r"(a0), "r"(a1), "r"(a2), "r"(a3), "r"(b0), "r"(b1));
}

// ---------------------------------------------------------------------------
// Kernel 1: LayerNorm over C + triangle-bias projection ([h][q][k] layout)
// ---------------------------------------------------------------------------
__global__ void k_ln_tri(const float* __restrict__ x,
                         const float* __restrict__ ln_w,
                         const float* __restrict__ ln_b,
                         const float* __restrict__ w_tri) {
    __shared__ float swt[H*C];
    int tid = threadIdx.x;
    swt[tid]       = w_tri[tid];
    swt[tid + 256] = w_tri[tid + 256];
    __syncthreads();

    int warp = tid >> 5, lane = tid & 31;
    int pos = (blockIdx.x << 3) + warp;

    const float4 a = ((const float4*)(x + (size_t)pos * C))[lane];
    float s  = a.x + a.y + a.z + a.w;
    float s2 = a.x*a.x + a.y*a.y + a.z*a.z + a.w*a.w;
#pragma unroll
    for (int o = 16; o > 0; o >>= 1) {
        s  += __shfl_xor_sync(0xffffffffu, s,  o);
        s2 += __shfl_xor_sync(0xffffffffu, s2, o);
    }
    float mu   = s * (1.0f / C);
    float var  = s2 * (1.0f / C) - mu * mu;
    float rstd = rsqrtf(var + EPSV);

    float4 w = ((const float4*)ln_w)[lane];
    float4 b = ((const float4*)ln_b)[lane];
    float4 xn;
    xn.x = (a.x - mu) * rstd * w.x + b.x;
    xn.y = (a.y - mu) * rstd * w.y + b.y;
    xn.z = (a.z - mu) * rstd * w.z + b.z;
    xn.w = (a.w - mu) * rstd * w.w + b.w;
    ((float4*)(g_xn + (size_t)pos * C))[lane] = xn;

    float t[H];
#pragma unroll
    for (int h = 0; h < H; ++h) {
        const float4 wt = ((const float4*)(swt + h * C))[lane];
        t[h] = xn.x*wt.x + xn.y*wt.y + xn.z*wt.z + xn.w*wt.w;
    }
#pragma unroll
    for (int h = 0; h < H; ++h)
#pragma unroll
        for (int o = 16; o > 0; o >>= 1)
            t[h] += __shfl_xor_sync(0xffffffffu, t[h], o);

    if (lane == 0) {
        int q = pos >> 8, k = pos & 255;
#pragma unroll
        for (int h = 0; h < H; ++h)
            g_tri[(h * N + q) * N + k] = t[h];   // [h][q][k]
    }
}

struct MmaAcc { float d[2][8][4]; };   // [mt][nt][reg]

// M-side streamed chunk (pitch 36), N-side resident (pitch 132, cbase offset)
__device__ __forceinline__ void mma_chunk_mres(const float (*Ac)[36], const float (*Br)[132],
                                               int cbase, int wm, int wn, int g, int tq,
                                               MmaAcc& A) {
#pragma unroll
    for (int ks = 0; ks < 32; ks += 8) {
        uint32_t af[2][4];
#pragma unroll
        for (int mt = 0; mt < 2; ++mt) {
            int r = wm * 32 + mt * 16;
            af[mt][0] = __float_as_uint(Ac[r + g][ks + tq]);
            af[mt][1] = __float_as_uint(Ac[r + g + 8][ks + tq]);
            af[mt][2] = __float_as_uint(Ac[r + g][ks + tq + 4]);
            af[mt][3] = __float_as_uint(Ac[r + g + 8][ks + tq + 4]);
        }
#pragma unroll
        for (int nt = 0; nt < 8; ++nt) {
            int cb = wn * 64 + nt * 8;
            uint32_t b0 = __float_as_uint(Br[cb + g][cbase + ks + tq]);
            uint32_t b1 = __float_as_uint(Br[cb + g][cbase + ks + tq + 4]);
#pragma unroll
            for (int mt = 0; mt < 2; ++mt)
                mma_tf32(A.d[mt][nt][0], A.d[mt][nt][1], A.d[mt][nt][2], A.d[mt][nt][3],
                         af[mt][0], af[mt][1], af[mt][2], af[mt][3], b0, b1);
        }
    }
}

// ---------------------------------------------------------------------------
// Kernel 2: fused K/V/Q/gate projection + MMA attention + gated epilogue.
// Block = (i, h), 256 threads (8 warps).
// Phase 1: [K|V|Q|gate] = xn[i] x W4_h via MMA, 32-row chunks, reg prefetch.
// Phase 2: per 64-query tile: S = Q K^T + tri + mask; softmax; O = P V;
//          epilogue applies sigmoid gate and writes gated output to g_o.
// ---------------------------------------------------------------------------
struct AttnSmem {
    union {
        struct {
            float W4[128][132];  // stacked [k|v|q|g] head weights  67584 B
            float Xs[32][132];   // xn chunk                        16896 B
        } p;                     // 84480 B
        float T[QT][260];        // tri bias -> P                   66560 B
    } u;                         // 84480 B
    float Ks[256][36];           // 36864 B
    float Vs[256][36];           // 36864 B
    float Qs[256][36];           // 36864 B (pre-scaled)
    float Gs[256][33];           // gate logits, raw fp32           33792 B
    float mb[256];               //  1024 B
    float rmax[QT][4];           //  1024 B
    float rsum[QT][4];           //  1024 B
};                               // 231936 B (<= 232448 opt-in)

__global__ void __launch_bounds__(256)
k_attn(const float* __restrict__ mask,
       const float* __restrict__ wq, const float* __restrict__ wk,
       const float* __restrict__ wv, const float* __restrict__ wg,
       const float* __restrict__ bg) {
    extern __shared__ char smraw[];
    AttnSmem* sm = (AttnSmem*)smraw;

    int i = blockIdx.x, h = blockIdx.y;
    int tid = threadIdx.x, w = tid >> 5, lane = tid & 31;
    int g = lane >> 2, tq = lane & 3;
    const float sc = 0.17677669529663688f;  // 1/sqrt(32)

    // ===================== Phase 1: project K/V/Q/gate =====================
    // W4 rows: 0-31 Wk_h, 32-63 Wv_h, 64-95 Wq_h, 96-127 Wg slice [h*32, h*32+32)
    {
        int pwm = w >> 2, pwn = w & 3;    // 2 warps M(32), 4 warps N(128)
#pragma unroll
        for (int t = 0; t < 16; ++t) {
            int idx = tid + t * 256;      // 0..4095
            int row = idx >> 5, j4 = idx & 31;
            const float* src = (row < 32) ? wk : (row < 64) ? wv : (row < 96) ? wq : wg;
            float4 b = *(const float4*)&src[(size_t)(h * 32 + (row & 31)) * C + j4 * 4];
            float4 r = {tf32r(b.x), tf32r(b.y), tf32r(b.z), tf32r(b.w)};
            *(float4*)&sm->u.p.W4[row][j4 * 4] = r;
        }
        sm->mb[tid] = INFV * (mask[i * N + tid] - 1.0f);

        // stage xn chunk 0 (32 rows)
        float4 xpre[4];
#pragma unroll
        for (int t = 0; t < 4; ++t) {
            int idx = tid + t * 256;      // 0..1023
            int row = idx >> 5, j4 = idx & 31;
            xpre[t] = *(const float4*)&g_xn[((size_t)(i * N + row)) * C + j4 * 4];
        }
#pragma unroll
        for (int t = 0; t < 4; ++t) {
            int idx = tid + t * 256;
            int row = idx >> 5, j4 = idx & 31;
            float4 r = {tf32r(xpre[t].x), tf32r(xpre[t].y), tf32r(xpre[t].z), tf32r(xpre[t].w)};
            *(float4*)&sm->u.p.Xs[row][j4 * 4] = r;
        }
        __syncthreads();

        for (int c = 0; c < 8; ++c) {
            // prefetch next chunk while doing MMAs
            if (c < 7) {
#pragma unroll
                for (int t = 0; t < 4; ++t) {
                    int idx = tid + t * 256;
                    int row = idx >> 5, j4 = idx & 31;
                    xpre[t] = *(const float4*)&g_xn[((size_t)(i * N + (c + 1) * 32 + row)) * C + j4 * 4];
                }
            }
            // GEMM: M=32 (xn rows), N=128 (k|v|q|gate), K=128. Warp tile 16x32.
            float pacc[4][4] = {};
#pragma unroll
            for (int ks = 0; ks < 128; ks += 8) {
                int r = pwm * 16;
                uint32_t a0 = __float_as_uint(sm->u.p.Xs[r + g][ks + tq]);
                uint32_t a1 = __float_as_uint(sm->u.p.Xs[r + g + 8][ks + tq]);
                uint32_t a2 = __float_as_uint(sm->u.p.Xs[r + g][ks + tq + 4]);
                uint32_t a3 = __float_as_uint(sm->u.p.Xs[r + g + 8][ks + tq + 4]);
#pragma unroll
                for (int nt = 0; nt < 4; ++nt) {
                    int cb = pwn * 32 + nt * 8;
                    uint32_t b0 = __float_as_uint(sm->u.p.W4[cb + g][ks + tq]);
                    uint32_t b1 = __float_as_uint(sm->u.p.W4[cb + g][ks + tq + 4]);
                    mma_tf32(pacc[nt][0], pacc[nt][1], pacc[nt][2], pacc[nt][3],
                             a0, a1, a2, a3, b0, b1);
                }
            }
            // scatter: pwn selects destination (0=K, 1=V, 2=Q scaled, 3=gate raw)
            {
                int row0 = c * 32 + pwm * 16 + g;
#pragma unroll
                for (int nt = 0; nt < 4; ++nt) {
                    int off = nt * 8 + 2 * tq;
                    float m0 = pacc[nt][0], m1 = pacc[nt][1];
                    float m2 = pacc[nt][2], m3 = pacc[nt][3];
                    if (pwn == 3) {
                        sm->Gs[row0][off]           = m0;
                        sm->Gs[row0][off + 1]       = m1;
                        sm->Gs[row0 + 8][off]       = m2;
                        sm->Gs[row0 + 8][off + 1]   = m3;
                    } else {
                        if (pwn == 2) { m0 *= sc; m1 *= sc; m2 *= sc; m3 *= sc; }
                        float* dst = (pwn == 0) ? &sm->Ks[0][0] :
                                     (pwn == 1) ? &sm->Vs[0][0] : &sm->Qs[0][0];
                        dst[row0 * 36 + off]           = tf32r(m0);
                        dst[row0 * 36 + off + 1]       = tf32r(m1);
                        dst[(row0 + 8) * 36 + off]     = tf32r(m2);
                        dst[(row0 + 8) * 36 + off + 1] = tf32r(m3);
                    }
                }
            }
            if (c < 7) {
                __syncthreads();   // all MMA reads of Xs done
#pragma unroll
                for (int t = 0; t < 4; ++t) {
                    int idx = tid + t * 256;
                    int row = idx >> 5, j4 = idx & 31;
                    float4 r = {tf32r(xpre[t].x), tf32r(xpre[t].y), tf32r(xpre[t].z), tf32r(xpre[t].w)};
                    *(float4*)&sm->u.p.Xs[row][j4 * 4] = r;
                }
                __syncthreads();
            }
        }
    }

    // ===================== Phase 2: attention =====================
    int wm = w >> 2, wn = w & 3;          // 2 warps along M(64), 4 along N(256)

    for (int qt = 0; qt < 4; ++qt) {
        int q0 = qt * QT;
        __syncthreads();   // phase1 / previous-qt done; T region free

        // ---- load tri tile [q0..q0+63][0..255] into T (fp32) ----
#pragma unroll
        for (int t = 0; t < 16; ++t) {
            int idx = tid + t * 256;           // 0..4095
            int row = idx >> 6, k4 = idx & 63;
            float4 tv = *(const float4*)&g_tri[((size_t)(h * N + q0 + row)) * N + k4 * 4];
            *(float4*)&sm->u.T[row][k4 * 4] = tv;
        }
        __syncthreads();

        // ---- S = Q K^T : warp tile 32x64, 2mt x 8nt, k=32 ----
        float sacc[2][8][4];
#pragma unroll
        for (int mt = 0; mt < 2; ++mt)
#pragma unroll
            for (int nt = 0; nt < 8; ++nt)
#pragma unroll
                for (int r = 0; r < 4; ++r) sacc[mt][nt][r] = 0.0f;

#pragma unroll
        for (int ks = 0; ks < 32; ks += 8) {
            uint32_t af[2][4];
#pragma unroll
            for (int mt = 0; mt < 2; ++mt) {
                int r = q0 + wm * 32 + mt * 16;
                af[mt][0] = __float_as_uint(sm->Qs[r + g][ks + tq]);
                af[mt][1] = __float_as_uint(sm->Qs[r + g + 8][ks + tq]);
                af[mt][2] = __float_as_uint(sm->Qs[r + g][ks + tq + 4]);
                af[mt][3] = __float_as_uint(sm->Qs[r + g + 8][ks + tq + 4]);
            }
#pragma unroll
            for (int nt = 0; nt < 8; ++nt) {
                int cb = wn * 64 + nt * 8;
                uint32_t b0 = __float_as_uint(sm->Ks[cb + g][ks + tq]);
                uint32_t b1 = __float_as_uint(sm->Ks[cb + g][ks + tq + 4]);
#pragma unroll
                for (int mt = 0; mt < 2; ++mt)
                    mma_tf32(sacc[mt][nt][0], sacc[mt][nt][1], sacc[mt][nt][2], sacc[mt][nt][3],
                             af[mt][0], af[mt][1], af[mt][2], af[mt][3], b0, b1);
            }
        }

        // ---- add tri + mask bias; partial row max ----
        float pmax[2][2];
        pmax[0][0] = pmax[0][1] = pmax[1][0] = pmax[1][1] = -3.4e38f;
#pragma unroll
        for (int mt = 0; mt < 2; ++mt) {
            int r0 = wm * 32 + mt * 16 + g;
#pragma unroll
            for (int nt = 0; nt < 8; ++nt) {
                int c0 = wn * 64 + nt * 8 + 2 * tq;
                float m0v = sm->mb[c0], m1v = sm->mb[c0 + 1];
                sacc[mt][nt][0] += sm->u.T[r0][c0]     + m0v;
                sacc[mt][nt][1] += sm->u.T[r0][c0 + 1] + m1v;
                sacc[mt][nt][2] += sm->u.T[r0 + 8][c0]     + m0v;
                sacc[mt][nt][3] += sm->u.T[r0 + 8][c0 + 1] + m1v;
                pmax[mt][0] = fmaxf(pmax[mt][0], fmaxf(sacc[mt][nt][0], sacc[mt][nt][1]));
                pmax[mt][1] = fmaxf(pmax[mt][1], fmaxf(sacc[mt][nt][2], sacc[mt][nt][3]));
            }
        }
#pragma unroll
        for (int mt = 0; mt < 2; ++mt)
#pragma unroll
            for (int rh = 0; rh < 2; ++rh) {
                float v = pmax[mt][rh];
                v = fmaxf(v, __shfl_xor_sync(0xffffffffu, v, 1));
                v = fmaxf(v, __shfl_xor_sync(0xffffffffu, v, 2));
                pmax[mt][rh] = v;
            }
        if (tq == 0) {
#pragma unroll
            for (int mt = 0; mt < 2; ++mt) {
                int r0 = wm * 32 + mt * 16 + g;
                sm->rmax[r0][wn]     = pmax[mt][0];
                sm->rmax[r0 + 8][wn] = pmax[mt][1];
            }
        }
        __syncthreads();

        // ---- exp + write P (tf32-rounded) + partial row sums ----
        float psum[2][2] = {{0.0f, 0.0f}, {0.0f, 0.0f}};
#pragma unroll
        for (int mt = 0; mt < 2; ++mt) {
            int r0 = wm * 32 + mt * 16 + g;
            float4 m4a = *(float4*)sm->rmax[r0];
            float rm0 = fmaxf(fmaxf(m4a.x, m4a.y), fmaxf(m4a.z, m4a.w));
            float4 m4b = *(float4*)sm->rmax[r0 + 8];
            float rm1 = fmaxf(fmaxf(m4b.x, m4b.y), fmaxf(m4b.z, m4b.w));
#pragma unroll
            for (int nt = 0; nt < 8; ++nt) {
                int c0 = wn * 64 + nt * 8 + 2 * tq;
                float p0 = tf32r(__expf(sacc[mt][nt][0] - rm0));
                float p1 = tf32r(__expf(sacc[mt][nt][1] - rm0));
                float p2 = tf32r(__expf(sacc[mt][nt][2] - rm1));
                float p3 = tf32r(__expf(sacc[mt][nt][3] - rm1));
                psum[mt][0] += p0 + p1;
                psum[mt][1] += p2 + p3;
                sm->u.T[r0][c0] = p0;     sm->u.T[r0][c0 + 1] = p1;
                sm->u.T[r0 + 8][c0] = p2; sm->u.T[r0 + 8][c0 + 1] = p3;
            }
        }
#pragma unroll
        for (int mt = 0; mt < 2; ++mt)
#pragma unroll
            for (int rh = 0; rh < 2; ++rh) {
                float v = psum[mt][rh];
                v += __shfl_xor_sync(0xffffffffu, v, 1);
                v += __shfl_xor_sync(0xffffffffu, v, 2);
                psum[mt][rh] = v;
            }
        if (tq == 0) {
#pragma unroll
            for (int mt = 0; mt < 2; ++mt) {
                int r0 = wm * 32 + mt * 16 + g;
                sm->rsum[r0][wn]     = psum[mt][0];
                sm->rsum[r0 + 8][wn] = psum[mt][1];
            }
        }
        __syncthreads();

        // ---- O = P V : warp tile 32x8, k=256 ----
        int nb = wn * 8;
        float oacc[2][4] = {{0,0,0,0},{0,0,0,0}};
#pragma unroll
        for (int ks8 = 0; ks8 < 32; ++ks8) {
            int kk = ks8 * 8;
            uint32_t b0 = __float_as_uint(sm->Vs[kk + tq][nb + g]);
            uint32_t b1 = __float_as_uint(sm->Vs[kk + tq + 4][nb + g]);
#pragma unroll
            for (int mt = 0; mt < 2; ++mt) {
                int r0 = wm * 32 + mt * 16 + g;
                uint32_t a0 = __float_as_uint(sm->u.T[r0][kk + tq]);
                uint32_t a1 = __float_as_uint(sm->u.T[r0 + 8][kk + tq]);
                uint32_t a2 = __float_as_uint(sm->u.T[r0][kk + tq + 4]);
                uint32_t a3 = __float_as_uint(sm->u.T[r0 + 8][kk + tq + 4]);
                mma_tf32(oacc[mt][0], oacc[mt][1], oacc[mt][2], oacc[mt][3],
                         a0, a1, a2, a3, b0, b1);
            }
        }

        // ---- epilogue: normalize, apply sigmoid gate, store gated output ----
#pragma unroll
        for (int mt = 0; mt < 2; ++mt) {
            int r0 = wm * 32 + mt * 16 + g;
            float4 s0 = *(float4*)sm->rsum[r0];
            float inv0 = 1.0f / (s0.x + s0.y + s0.z + s0.w);
            float4 s1 = *(float4*)sm->rsum[r0 + 8];
            float inv1 = 1.0f / (s1.x + s1.y + s1.z + s1.w);
            int col = nb + 2 * tq;
            float bga = bg[h * 32 + col], bgb = bg[h * 32 + col + 1];
            int gr0 = q0 + r0, gr1 = q0 + r0 + 8;
            float d00 = 1.0f + __expf(-(sm->Gs[gr0][col]     + bga));
            float d01 = 1.0f + __expf(-(sm->Gs[gr0][col + 1] + bgb));
            float d10 = 1.0f + __expf(-(sm->Gs[gr1][col]     + bga));
            float d11 = 1.0f + __expf(-(sm->Gs[gr1][col + 1] + bgb));
            size_t b0a = ((size_t)(i * N + gr0)) * C + h * D + col;
            *(float2*)&g_o[b0a] = make_float2((oacc[mt][0] * inv0) / d00,
                                              (oacc[mt][1] * inv0) / d01);
            size_t b1a = ((size_t)(i * N + gr1)) * C + h * D + col;
            *(float2*)&g_o[b1a] = make_float2((oacc[mt][2] * inv1) / d10,
                                              (oacc[mt][3] * inv1) / d11);
        }
    }
}

// ---------------------------------------------------------------------------
// Kernel 3: output projection. grid=NP/128.
// B (wo) resident; A (already-gated o) streamed with register prefetch.
// ---------------------------------------------------------------------------
struct OutSmem {
    float Bs[128][132];     // resident wo        67584 B
    float As[2][128][36];   // A chunks           36864 B
};                          // 104448 B

__global__ void __launch_bounds__(256)
k_out(const float* __restrict__ wo, const float* __restrict__ bo,
      float* __restrict__ out) {
    extern __shared__ char smraw[];
    OutSmem* sm = (OutSmem*)smraw;
    int tid = threadIdx.x;
    int m0 = blockIdx.x * 128;
    int w = tid >> 5, lane = tid & 31;
    int wm = w >> 1, wn = w & 1;
    int g = lane >> 2, tq = lane & 3;

#pragma unroll
    for (int t = 0; t < 16; ++t) {
        int idx = tid + t * 256;
        int row = idx >> 5, j4 = idx & 31;
        float4 b = *(const float4*)&wo[(size_t)row * C + j4 * 4];
        float4 r = {tf32r(b.x), tf32r(b.y), tf32r(b.z), tf32r(b.w)};
        *(float4*)&sm->Bs[row][j4 * 4] = r;
    }
#pragma unroll
    for (int t = 0; t < 4; ++t) {
        int idx = tid + t * 256;
        int row = idx >> 3, j = idx & 7;
        float4 ov = *(const float4*)&g_o[(size_t)(m0 + row) * C + j * 4];
        float4 r = {tf32r(ov.x), tf32r(ov.y), tf32r(ov.z), tf32r(ov.w)};
        *(float4*)&sm->As[0][row][j * 4] = r;
    }
    __syncthreads();

    MmaAcc acc;
#pragma unroll
    for (int mt = 0; mt < 2; ++mt)
#pragma unroll
        for (int nt = 0; nt < 8; ++nt)
#pragma unroll
            for (int r = 0; r < 4; ++r) acc.d[mt][nt][r] = 0.0f;

    for (int kc = 0; kc < 4; ++kc) {
        float4 po[4];
        if (kc < 3) {
#pragma unroll
            for (int t = 0; t < 4; ++t) {
                int idx = tid + t * 256;
                int row = idx >> 3, j = idx & 7;
                po[t] = *(const float4*)&g_o[(size_t)(m0 + row) * C + (kc + 1) * 32 + j * 4];
            }
        }
        mma_chunk_mres(sm->As[kc & 1], sm->Bs, kc * 32, wm, wn, g, tq, acc);
        if (kc < 3) {
#pragma unroll
            for (int t = 0; t < 4; ++t) {
                int idx = tid + t * 256;
                int row = idx >> 3, j = idx & 7;
                float4 r = {tf32r(po[t].x), tf32r(po[t].y), tf32r(po[t].z), tf32r(po[t].w)};
                *(float4*)&sm->As[(kc + 1) & 1][row][j * 4] = r;
            }
            __syncthreads();
        }
    }

#pragma unroll
    for (int mt = 0; mt < 2; ++mt) {
        int r0 = m0 + wm * 32 + mt * 16 + g;
#pragma unroll
        for (int nt = 0; nt < 8; ++nt) {
            int cb = wn * 64 + nt * 8 + 2 * tq;
            float2 bov = *(const float2*)&bo[cb];
            *(float2*)&out[(size_t)r0 * C + cb] =
                make_float2(acc.d[mt][nt][0] + bov.x, acc.d[mt][nt][1] + bov.y);
            *(float2*)&out[(size_t)(r0 + 8) * C + cb] =
                make_float2(acc.d[mt][nt][2] + bov.x, acc.d[mt][nt][3] + bov.y);
        }
    }
}

// ---------------------------------------------------------------------------
extern "C" void kernel_launch(void* const* d_in, const int* in_sizes, int n_in,
                              void* d_out, int out_size) {
    const float* x     = (const float*)d_in[0];
    const float* mask  = (const float*)d_in[1];
    const float* ln_w  = (const float*)d_in[2];
    const float* ln_b  = (const float*)d_in[3];
    const float* w_tri = (const float*)d_in[4];
    const float* wq    = (const float*)d_in[5];
    const float* wk    = (const float*)d_in[6];
    const float* wv    = (const float*)d_in[7];
    const float* wg    = (const float*)d_in[8];
    const float* bg    = (const float*)d_in[9];
    const float* wo    = (const float*)d_in[10];
    const float* bo    = (const float*)d_in[11];
    float* out = (float*)d_out;

    (void)in_sizes; (void)n_in; (void)out_size;

    cudaFuncSetAttribute(k_out, cudaFuncAttributeMaxDynamicSharedMemorySize,
                         (int)sizeof(OutSmem));
    cudaFuncSetAttribute(k_attn, cudaFuncAttributeMaxDynamicSharedMemorySize,
                         (int)sizeof(AttnSmem));

    k_ln_tri<<<NP / 8, 256>>>(x, ln_w, ln_b, w_tri);
    k_attn<<<dim3(N, H), 256, sizeof(AttnSmem)>>>(mask, wq, wk, wv, wg, bg);
    k_out<<<NP / 128, 256, sizeof(OutSmem)>>>(wo, bo, out);
}

// round 13
// speedup vs baseline: 1.0469x; 1.0017x over previous
#include <cuda_runtime.h>
#include <math.h>
#include <stdint.h>

#define N 256
#define C 128
#define H 4
#define D 32
#define NP (N*N)            // 65536 positions
#define EPSV 1e-5f
#define INFV 1000000000.0f
#define QT 64               // attention query tile

// Scratch (static device arrays; no allocation in kernel_launch)
__device__ float g_xn[NP*C];        // layernormed x, tf32-pre-rounded  32 MB
__device__ float g_tri[H*N*N];      // tri bias [h][q][k]                1 MB
__device__ float g_o[NP*C];         // gated attention output           32 MB

// round fp32 -> tf32 bit pattern (rna), returned as float bits
__device__ __forceinline__ float tf32r(float x) {
    uint32_t u;
    asm("cvt.rna.tf32.f32 %0, %1;" : "=r"(u) : "f"(x));
    return __uint_as_float(u);
}

__device__ __forceinline__ void mma_tf32(float& d0, float& d1, float& d2, float& d3,
                                         uint32_t a0, uint32_t a1, uint32_t a2, uint32_t a3,
                                         uint32_t b0, uint32_t b1) {
    asm volatile(
        "mma.sync.aligned.m16n8k8.row.col.f32.tf32.tf32.f32 "
        "{%0,%1,%2,%3}, {%4,%5,%6,%7}, {%8,%9}, {%0,%1,%2,%3};\n"
        : "+f"(d0), "+f"(d1), "+f"(d2), "+f"(d3)
        : "r"(a0), "r"(a1), "r"(a2), "r"(a3), "r"(b0), "r"(b1));
}

// ---------------------------------------------------------------------------
// Kernel 1: LayerNorm over C + triangle-bias projection ([h][q][k] layout).
// g_xn is stored tf32-pre-rounded (tri uses unrounded values).
// Packed 4-head tri reduction: 6 shuffles instead of 20.
// ---------------------------------------------------------------------------
__global__ void k_ln_tri(const float* __restrict__ x,
                         const float* __restrict__ ln_w,
                         const float* __restrict__ ln_b,
                         const float* __restrict__ w_tri) {
    __shared__ float swt[H*C];
    int tid = threadIdx.x;
    swt[tid]       = w_tri[tid];
    swt[tid + 256] = w_tri[tid + 256];
    __syncthreads();

    int warp = tid >> 5, lane = tid & 31;
    int pos = (blockIdx.x << 3) + warp;

    const float4 a = ((const float4*)(x + (size_t)pos * C))[lane];
    float s  = a.x + a.y + a.z + a.w;
    float s2 = a.x*a.x + a.y*a.y + a.z*a.z + a.w*a.w;
#pragma unroll
    for (int o = 16; o > 0; o >>= 1) {
        s  += __shfl_xor_sync(0xffffffffu, s,  o);
        s2 += __shfl_xor_sync(0xffffffffu, s2, o);
    }
    float mu   = s * (1.0f / C);
    float var  = s2 * (1.0f / C) - mu * mu;
    float rstd = rsqrtf(var + EPSV);

    float4 w = ((const float4*)ln_w)[lane];
    float4 b = ((const float4*)ln_b)[lane];
    float4 xn;
    xn.x = (a.x - mu) * rstd * w.x + b.x;
    xn.y = (a.y - mu) * rstd * w.y + b.y;
    xn.z = (a.z - mu) * rstd * w.z + b.z;
    xn.w = (a.w - mu) * rstd * w.w + b.w;
    // store tf32-pre-rounded (k_attn consumes these bits directly)
    float4 xr = {tf32r(xn.x), tf32r(xn.y), tf32r(xn.z), tf32r(xn.w)};
    ((float4*)(g_xn + (size_t)pos * C))[lane] = xr;

    // tri from UNROUNDED xn
    float t0, t1, t2, t3;
    {
        const float4 w0 = ((const float4*)(swt + 0 * C))[lane];
        const float4 w1 = ((const float4*)(swt + 1 * C))[lane];
        const float4 w2 = ((const float4*)(swt + 2 * C))[lane];
        const float4 w3 = ((const float4*)(swt + 3 * C))[lane];
        t0 = xn.x*w0.x + xn.y*w0.y + xn.z*w0.z + xn.w*w0.w;
        t1 = xn.x*w1.x + xn.y*w1.y + xn.z*w1.z + xn.w*w1.w;
        t2 = xn.x*w2.x + xn.y*w2.y + xn.z*w2.z + xn.w*w2.w;
        t3 = xn.x*w3.x + xn.y*w3.y + xn.z*w3.z + xn.w*w3.w;
    }
    // packed reduction: after 3 stages lane&3 indexes the head
    bool o1 = lane & 1;
    float a01 = o1 ? t1 : t0;
    float b01 = o1 ? t0 : t1;
    a01 += __shfl_xor_sync(0xffffffffu, b01, 1);
    float a23 = o1 ? t3 : t2;
    float b23 = o1 ? t2 : t3;
    a23 += __shfl_xor_sync(0xffffffffu, b23, 1);
    bool o2 = lane & 2;
    float cc = o2 ? a23 : a01;
    float dd = o2 ? a01 : a23;
    cc += __shfl_xor_sync(0xffffffffu, dd, 2);
    cc += __shfl_xor_sync(0xffffffffu, cc, 4);
    cc += __shfl_xor_sync(0xffffffffu, cc, 8);
    cc += __shfl_xor_sync(0xffffffffu, cc, 16);

    if (lane < 4) {
        int q = pos >> 8, k = pos & 255;
        g_tri[((size_t)(lane * N + q)) * N + k] = cc;   // head = lane
    }
}

struct MmaAcc { float d[2][8][4]; };   // [mt][nt][reg]

// M-side streamed chunk (pitch 36), N-side resident (pitch 132, cbase offset)
__device__ __forceinline__ void mma_chunk_mres(const float (*Ac)[36], const float (*Br)[132],
                                               int cbase, int wm, int wn, int g, int tq,
                                               MmaAcc& A) {
#pragma unroll
    for (int ks = 0; ks < 32; ks += 8) {
        uint32_t af[2][4];
#pragma unroll
        for (int mt = 0; mt < 2; ++mt) {
            int r = wm * 32 + mt * 16;
            af[mt][0] = __float_as_uint(Ac[r + g][ks + tq]);
            af[mt][1] = __float_as_uint(Ac[r + g + 8][ks + tq]);
            af[mt][2] = __float_as_uint(Ac[r + g][ks + tq + 4]);
            af[mt][3] = __float_as_uint(Ac[r + g + 8][ks + tq + 4]);
        }
#pragma unroll
        for (int nt = 0; nt < 8; ++nt) {
            int cb = wn * 64 + nt * 8;
            uint32_t b0 = __float_as_uint(Br[cb + g][cbase + ks + tq]);
            uint32_t b1 = __float_as_uint(Br[cb + g][cbase + ks + tq + 4]);
#pragma unroll
            for (int mt = 0; mt < 2; ++mt)
                mma_tf32(A.d[mt][nt][0], A.d[mt][nt][1], A.d[mt][nt][2], A.d[mt][nt][3],
                         af[mt][0], af[mt][1], af[mt][2], af[mt][3], b0, b1);
        }
    }
}

// ---------------------------------------------------------------------------
// Kernel 2: fused K/V/Q/gate projection + MMA attention + gated epilogue.
// Block = (i, h), 256 threads (8 warps).
// ---------------------------------------------------------------------------
struct AttnSmem {
    union {
        struct {
            float W4[128][132];  // stacked [k|v|q|g] head weights  67584 B
            float Xs[32][132];   // xn chunk                        16896 B
        } p;                     // 84480 B
        float T[QT][260];        // tri bias -> P                   66560 B
    } u;                         // 84480 B
    float Ks[256][36];           // 36864 B
    float Vs[256][36];           // 36864 B
    float Qs[256][36];           // 36864 B (pre-scaled)
    float Gs[256][33];           // gate logits, raw fp32           33792 B
    float mb[256];               //  1024 B
    float rmax[QT][4];           //  1024 B
    float rsum[QT][4];           //  1024 B
};                               // 231936 B (<= 232448 opt-in)

__global__ void __launch_bounds__(256)
k_attn(const float* __restrict__ mask,
       const float* __restrict__ wq, const float* __restrict__ wk,
       const float* __restrict__ wv, const float* __restrict__ wg,
       const float* __restrict__ bg) {
    extern __shared__ char smraw[];
    AttnSmem* sm = (AttnSmem*)smraw;

    int i = blockIdx.x, h = blockIdx.y;
    int tid = threadIdx.x, w = tid >> 5, lane = tid & 31;
    int g = lane >> 2, tq = lane & 3;
    const float sc = 0.17677669529663688f;  // 1/sqrt(32)

    // ===================== Phase 1: project K/V/Q/gate =====================
    // W4 rows: 0-31 Wk_h, 32-63 Wv_h, 64-95 Wq_h, 96-127 Wg slice [h*32, h*32+32)
    {
        int pwm = w >> 2, pwn = w & 3;    // 2 warps M(32), 4 warps N(128)
#pragma unroll
        for (int t = 0; t < 16; ++t) {
            int idx = tid + t * 256;      // 0..4095
            int row = idx >> 5, j4 = idx & 31;
            const float* src = (row < 32) ? wk : (row < 64) ? wv : (row < 96) ? wq : wg;
            float4 b = *(const float4*)&src[(size_t)(h * 32 + (row & 31)) * C + j4 * 4];
            float4 r = {tf32r(b.x), tf32r(b.y), tf32r(b.z), tf32r(b.w)};
            *(float4*)&sm->u.p.W4[row][j4 * 4] = r;
        }
        sm->mb[tid] = INFV * (mask[i * N + tid] - 1.0f);

        // stage xn chunk 0 (32 rows) — g_xn is pre-rounded, copy raw
        float4 xpre[4];
#pragma unroll
        for (int t = 0; t < 4; ++t) {
            int idx = tid + t * 256;      // 0..1023
            int row = idx >> 5, j4 = idx & 31;
            xpre[t] = *(const float4*)&g_xn[((size_t)(i * N + row)) * C + j4 * 4];
        }
#pragma unroll
        for (int t = 0; t < 4; ++t) {
            int idx = tid + t * 256;
            int row = idx >> 5, j4 = idx & 31;
            *(float4*)&sm->u.p.Xs[row][j4 * 4] = xpre[t];
        }
        __syncthreads();

        for (int c = 0; c < 8; ++c) {
            // prefetch next chunk while doing MMAs
            if (c < 7) {
#pragma unroll
                for (int t = 0; t < 4; ++t) {
                    int idx = tid + t * 256;
                    int row = idx >> 5, j4 = idx & 31;
                    xpre[t] = *(const float4*)&g_xn[((size_t)(i * N + (c + 1) * 32 + row)) * C + j4 * 4];
                }
            }
            // GEMM: M=32 (xn rows), N=128 (k|v|q|gate), K=128. Warp tile 16x32.
            float pacc[4][4] = {};
#pragma unroll
            for (int ks = 0; ks < 128; ks += 8) {
                int r = pwm * 16;
                uint32_t a0 = __float_as_uint(sm->u.p.Xs[r + g][ks + tq]);
                uint32_t a1 = __float_as_uint(sm->u.p.Xs[r + g + 8][ks + tq]);
                uint32_t a2 = __float_as_uint(sm->u.p.Xs[r + g][ks + tq + 4]);
                uint32_t a3 = __float_as_uint(sm->u.p.Xs[r + g + 8][ks + tq + 4]);
#pragma unroll
                for (int nt = 0; nt < 4; ++nt) {
                    int cb = pwn * 32 + nt * 8;
                    uint32_t b0 = __float_as_uint(sm->u.p.W4[cb + g][ks + tq]);
                    uint32_t b1 = __float_as_uint(sm->u.p.W4[cb + g][ks + tq + 4]);
                    mma_tf32(pacc[nt][0], pacc[nt][1], pacc[nt][2], pacc[nt][3],
                             a0, a1, a2, a3, b0, b1);
                }
            }
            // scatter: pwn selects destination (0=K, 1=V, 2=Q scaled, 3=gate raw)
            {
                int row0 = c * 32 + pwm * 16 + g;
#pragma unroll
                for (int nt = 0; nt < 4; ++nt) {
                    int off = nt * 8 + 2 * tq;
                    float m0 = pacc[nt][0], m1 = pacc[nt][1];
                    float m2 = pacc[nt][2], m3 = pacc[nt][3];
                    if (pwn == 3) {
                        sm->Gs[row0][off]           = m0;
                        sm->Gs[row0][off + 1]       = m1;
                        sm->Gs[row0 + 8][off]       = m2;
                        sm->Gs[row0 + 8][off + 1]   = m3;
                    } else {
                        if (pwn == 2) { m0 *= sc; m1 *= sc; m2 *= sc; m3 *= sc; }
                        float* dst = (pwn == 0) ? &sm->Ks[0][0] :
                                     (pwn == 1) ? &sm->Vs[0][0] : &sm->Qs[0][0];
                        dst[row0 * 36 + off]           = tf32r(m0);
                        dst[row0 * 36 + off + 1]       = tf32r(m1);
                        dst[(row0 + 8) * 36 + off]     = tf32r(m2);
                        dst[(row0 + 8) * 36 + off + 1] = tf32r(m3);
                    }
                }
            }
            if (c < 7) {
                __syncthreads();   // all MMA reads of Xs done
#pragma unroll
                for (int t = 0; t < 4; ++t) {
                    int idx = tid + t * 256;
                    int row = idx >> 5, j4 = idx & 31;
                    *(float4*)&sm->u.p.Xs[row][j4 * 4] = xpre[t];
                }
                __syncthreads();
            }
        }
    }

    // ===================== Phase 2: attention =====================
    int wm = w >> 2, wn = w & 3;          // 2 warps along M(64), 4 along N(256)

    for (int qt = 0; qt < 4; ++qt) {
        int q0 = qt * QT;
        __syncthreads();   // phase1 / previous-qt done; T region free

        // ---- load tri tile [q0..q0+63][0..255] into T (fp32) ----
#pragma unroll
        for (int t = 0; t < 16; ++t) {
            int idx = tid + t * 256;           // 0..4095
            int row = idx >> 6, k4 = idx & 63;
            float4 tv = *(const float4*)&g_tri[((size_t)(h * N + q0 + row)) * N + k4 * 4];
            *(float4*)&sm->u.T[row][k4 * 4] = tv;
        }
        __syncthreads();

        // ---- S = Q K^T : warp tile 32x64, 2mt x 8nt, k=32 ----
        float sacc[2][8][4];
#pragma unroll
        for (int mt = 0; mt < 2; ++mt)
#pragma unroll
            for (int nt = 0; nt < 8; ++nt)
#pragma unroll
                for (int r = 0; r < 4; ++r) sacc[mt][nt][r] = 0.0f;

#pragma unroll
        for (int ks = 0; ks < 32; ks += 8) {
            uint32_t af[2][4];
#pragma unroll
            for (int mt = 0; mt < 2; ++mt) {
                int r = q0 + wm * 32 + mt * 16;
                af[mt][0] = __float_as_uint(sm->Qs[r + g][ks + tq]);
                af[mt][1] = __float_as_uint(sm->Qs[r + g + 8][ks + tq]);
                af[mt][2] = __float_as_uint(sm->Qs[r + g][ks + tq + 4]);
                af[mt][3] = __float_as_uint(sm->Qs[r + g + 8][ks + tq + 4]);
            }
#pragma unroll
            for (int nt = 0; nt < 8; ++nt) {
                int cb = wn * 64 + nt * 8;
                uint32_t b0 = __float_as_uint(sm->Ks[cb + g][ks + tq]);
                uint32_t b1 = __float_as_uint(sm->Ks[cb + g][ks + tq + 4]);
#pragma unroll
                for (int mt = 0; mt < 2; ++mt)
                    mma_tf32(sacc[mt][nt][0], sacc[mt][nt][1], sacc[mt][nt][2], sacc[mt][nt][3],
                             af[mt][0], af[mt][1], af[mt][2], af[mt][3], b0, b1);
            }
        }

        // ---- add tri + mask bias; partial row max ----
        float pmax[2][2];
        pmax[0][0] = pmax[0][1] = pmax[1][0] = pmax[1][1] = -3.4e38f;
#pragma unroll
        for (int mt = 0; mt < 2; ++mt) {
            int r0 = wm * 32 + mt * 16 + g;
#pragma unroll
            for (int nt = 0; nt < 8; ++nt) {
                int c0 = wn * 64 + nt * 8 + 2 * tq;
                float m0v = sm->mb[c0], m1v = sm->mb[c0 + 1];
                sacc[mt][nt][0] += sm->u.T[r0][c0]     + m0v;
                sacc[mt][nt][1] += sm->u.T[r0][c0 + 1] + m1v;
                sacc[mt][nt][2] += sm->u.T[r0 + 8][c0]     + m0v;
                sacc[mt][nt][3] += sm->u.T[r0 + 8][c0 + 1] + m1v;
                pmax[mt][0] = fmaxf(pmax[mt][0], fmaxf(sacc[mt][nt][0], sacc[mt][nt][1]));
                pmax[mt][1] = fmaxf(pmax[mt][1], fmaxf(sacc[mt][nt][2], sacc[mt][nt][3]));
            }
        }
#pragma unroll
        for (int mt = 0; mt < 2; ++mt)
#pragma unroll
            for (int rh = 0; rh < 2; ++rh) {
                float v = pmax[mt][rh];
                v = fmaxf(v, __shfl_xor_sync(0xffffffffu, v, 1));
                v = fmaxf(v, __shfl_xor_sync(0xffffffffu, v, 2));
                pmax[mt][rh] = v;
            }
        if (tq == 0) {
#pragma unroll
            for (int mt = 0; mt < 2; ++mt) {
                int r0 = wm * 32 + mt * 16 + g;
                sm->rmax[r0][wn]     = pmax[mt][0];
                sm->rmax[r0 + 8][wn] = pmax[mt][1];
            }
        }
        __syncthreads();

        // ---- exp + write P (tf32-rounded) + partial row sums ----
        float psum[2][2] = {{0.0f, 0.0f}, {0.0f, 0.0f}};
#pragma unroll
        for (int mt = 0; mt < 2; ++mt) {
            int r0 = wm * 32 + mt * 16 + g;
            float4 m4a = *(float4*)sm->rmax[r0];
            float rm0 = fmaxf(fmaxf(m4a.x, m4a.y), fmaxf(m4a.z, m4a.w));
            float4 m4b = *(float4*)sm->rmax[r0 + 8];
            float rm1 = fmaxf(fmaxf(m4b.x, m4b.y), fmaxf(m4b.z, m4b.w));
#pragma unroll
            for (int nt = 0; nt < 8; ++nt) {
                int c0 = wn * 64 + nt * 8 + 2 * tq;
                float p0 = tf32r(__expf(sacc[mt][nt][0] - rm0));
                float p1 = tf32r(__expf(sacc[mt][nt][1] - rm0));
                float p2 = tf32r(__expf(sacc[mt][nt][2] - rm1));
                float p3 = tf32r(__expf(sacc[mt][nt][3] - rm1));
                psum[mt][0] += p0 + p1;
                psum[mt][1] += p2 + p3;
                sm->u.T[r0][c0] = p0;     sm->u.T[r0][c0 + 1] = p1;
                sm->u.T[r0 + 8][c0] = p2; sm->u.T[r0 + 8][c0 + 1] = p3;
            }
        }
#pragma unroll
        for (int mt = 0; mt < 2; ++mt)
#pragma unroll
            for (int rh = 0; rh < 2; ++rh) {
                float v = psum[mt][rh];
                v += __shfl_xor_sync(0xffffffffu, v, 1);
                v += __shfl_xor_sync(0xffffffffu, v, 2);
                psum[mt][rh] = v;
            }
        if (tq == 0) {
#pragma unroll
            for (int mt = 0; mt < 2; ++mt) {
                int r0 = wm * 32 + mt * 16 + g;
                sm->rsum[r0][wn]     = psum[mt][0];
                sm->rsum[r0 + 8][wn] = psum[mt][1];
            }
        }
        __syncthreads();

        // ---- O = P V : warp tile 32x8, k=256 ----
        int nb = wn * 8;
        float oacc[2][4] = {{0,0,0,0},{0,0,0,0}};
#pragma unroll
        for (int ks8 = 0; ks8 < 32; ++ks8) {
            int kk = ks8 * 8;
            uint32_t b0 = __float_as_uint(sm->Vs[kk + tq][nb + g]);
            uint32_t b1 = __float_as_uint(sm->Vs[kk + tq + 4][nb + g]);
#pragma unroll
            for (int mt = 0; mt < 2; ++mt) {
                int r0 = wm * 32 + mt * 16 + g;
                uint32_t a0 = __float_as_uint(sm->u.T[r0][kk + tq]);
                uint32_t a1 = __float_as_uint(sm->u.T[r0 + 8][kk + tq]);
                uint32_t a2 = __float_as_uint(sm->u.T[r0][kk + tq + 4]);
                uint32_t a3 = __float_as_uint(sm->u.T[r0 + 8][kk + tq + 4]);
                mma_tf32(oacc[mt][0], oacc[mt][1], oacc[mt][2], oacc[mt][3],
                         a0, a1, a2, a3, b0, b1);
            }
        }

        // ---- epilogue: normalize, apply sigmoid gate, store gated output ----
#pragma unroll
        for (int mt = 0; mt < 2; ++mt) {
            int r0 = wm * 32 + mt * 16 + g;
            float4 s0 = *(float4*)sm->rsum[r0];
            float inv0 = 1.0f / (s0.x + s0.y + s0.z + s0.w);
            float4 s1 = *(float4*)sm->rsum[r0 + 8];
            float inv1 = 1.0f / (s1.x + s1.y + s1.z + s1.w);
            int col = nb + 2 * tq;
            float bga = bg[h * 32 + col], bgb = bg[h * 32 + col + 1];
            int gr0 = q0 + r0, gr1 = q0 + r0 + 8;
            float d00 = 1.0f + __expf(-(sm->Gs[gr0][col]     + bga));
            float d01 = 1.0f + __expf(-(sm->Gs[gr0][col + 1] + bgb));
            float d10 = 1.0f + __expf(-(sm->Gs[gr1][col]     + bga));
            float d11 = 1.0f + __expf(-(sm->Gs[gr1][col + 1] + bgb));
            size_t b0a = ((size_t)(i * N + gr0)) * C + h * D + col;
            *(float2*)&g_o[b0a] = make_float2((oacc[mt][0] * inv0) / d00,
                                              (oacc[mt][1] * inv0) / d01);
            size_t b1a = ((size_t)(i * N + gr1)) * C + h * D + col;
            *(float2*)&g_o[b1a] = make_float2((oacc[mt][2] * inv1) / d10,
                                              (oacc[mt][3] * inv1) / d11);
        }
    }
}

// ---------------------------------------------------------------------------
// Kernel 3: output projection. grid=NP/128, 2 blocks/SM.
// B (wo) resident; A (already-gated o) streamed with register prefetch.
// ---------------------------------------------------------------------------
struct OutSmem {
    float Bs[128][132];     // resident wo        67584 B
    float As[2][128][36];   // A chunks           36864 B
};                          // 104448 B

__global__ void __launch_bounds__(256, 2)
k_out(const float* __restrict__ wo, const float* __restrict__ bo,
      float* __restrict__ out) {
    extern __shared__ char smraw[];
    OutSmem* sm = (OutSmem*)smraw;
    int tid = threadIdx.x;
    int m0 = blockIdx.x * 128;
    int w = tid >> 5, lane = tid & 31;
    int wm = w >> 1, wn = w & 1;
    int g = lane >> 2, tq = lane & 3;

#pragma unroll
    for (int t = 0; t < 16; ++t) {
        int idx = tid + t * 256;
        int row = idx >> 5, j4 = idx & 31;
        float4 b = *(const float4*)&wo[(size_t)row * C + j4 * 4];
        float4 r = {tf32r(b.x), tf32r(b.y), tf32r(b.z), tf32r(b.w)};
        *(float4*)&sm->Bs[row][j4 * 4] = r;
    }
#pragma unroll
    for (int t = 0; t < 4; ++t) {
        int idx = tid + t * 256;
        int row = idx >> 3, j = idx & 7;
        float4 ov = *(const float4*)&g_o[(size_t)(m0 + row) * C + j * 4];
        float4 r = {tf32r(ov.x), tf32r(ov.y), tf32r(ov.z), tf32r(ov.w)};
        *(float4*)&sm->As[0][row][j * 4] = r;
    }
    __syncthreads();

    MmaAcc acc;
#pragma unroll
    for (int mt = 0; mt < 2; ++mt)
#pragma unroll
        for (int nt = 0; nt < 8; ++nt)
#pragma unroll
            for (int r = 0; r < 4; ++r) acc.d[mt][nt][r] = 0.0f;

    for (int kc = 0; kc < 4; ++kc) {
        float4 po[4];
        if (kc < 3) {
#pragma unroll
            for (int t = 0; t < 4; ++t) {
                int idx = tid + t * 256;
                int row = idx >> 3, j = idx & 7;
                po[t] = *(const float4*)&g_o[(size_t)(m0 + row) * C + (kc + 1) * 32 + j * 4];
            }
        }
        mma_chunk_mres(sm->As[kc & 1], sm->Bs, kc * 32, wm, wn, g, tq, acc);
        if (kc < 3) {
#pragma unroll
            for (int t = 0; t < 4; ++t) {
                int idx = tid + t * 256;
                int row = idx >> 3, j = idx & 7;
                float4 r = {tf32r(po[t].x), tf32r(po[t].y), tf32r(po[t].z), tf32r(po[t].w)};
                *(float4*)&sm->As[(kc + 1) & 1][row][j * 4] = r;
            }
            __syncthreads();
        }
    }

#pragma unroll
    for (int mt = 0; mt < 2; ++mt) {
        int r0 = m0 + wm * 32 + mt * 16 + g;
#pragma unroll
        for (int nt = 0; nt < 8; ++nt) {
            int cb = wn * 64 + nt * 8 + 2 * tq;
            float2 bov = *(const float2*)&bo[cb];
            *(float2*)&out[(size_t)r0 * C + cb] =
                make_float2(acc.d[mt][nt][0] + bov.x, acc.d[mt][nt][1] + bov.y);
            *(float2*)&out[(size_t)(r0 + 8) * C + cb] =
                make_float2(acc.d[mt][nt][2] + bov.x, acc.d[mt][nt][3] + bov.y);
        }
    }
}

// ---------------------------------------------------------------------------
extern "C" void kernel_launch(void* const* d_in, const int* in_sizes, int n_in,
                              void* d_out, int out_size) {
    const float* x     = (const float*)d_in[0];
    const float* mask  = (const float*)d_in[1];
    const float* ln_w  = (const float*)d_in[2];
    const float* ln_b  = (const float*)d_in[3];
    const float* w_tri = (const float*)d_in[4];
    const float* wq    = (const float*)d_in[5];
    const float* wk    = (const float*)d_in[6];
    const float* wv    = (const float*)d_in[7];
    const float* wg    = (const float*)d_in[8];
    const float* bg    = (const float*)d_in[9];
    const float* wo    = (const float*)d_in[10];
    const float* bo    = (const float*)d_in[11];
    float* out = (float*)d_out;

    (void)in_sizes; (void)n_in; (void)out_size;

    cudaFuncSetAttribute(k_out, cudaFuncAttributeMaxDynamicSharedMemorySize,
                         (int)sizeof(OutSmem));
    cudaFuncSetAttribute(k_attn, cudaFuncAttributeMaxDynamicSharedMemorySize,
                         (int)sizeof(AttnSmem));

    k_ln_tri<<<NP / 8, 256>>>(x, ln_w, ln_b, w_tri);
    k_attn<<<dim3(N, H), 256, sizeof(AttnSmem)>>>(mask, wq, wk, wv, wg, bg);
    k_out<<<NP / 128, 256, sizeof(OutSmem)>>>(wo, bo, out);
}

// round 14
// speedup vs baseline: 1.4082x; 1.3451x over previous
#include <cuda_runtime.h>
#include <cuda_fp16.h>
#include <math.h>
#include <stdint.h>

#define N 256
#define C 128
#define H 4
#define D 32
#define NP (N*N)            // 65536 positions
#define EPSV 1e-5f
#define INFV 1000000000.0f
#define QT 64               // attention query tile

// Scratch (static device arrays; no allocation in kernel_launch)
__device__ float g_xn[NP*C];        // layernormed x, tf32-pre-rounded  32 MB
__device__ float g_tri[H*N*N];      // tri bias [h][q][k]                1 MB
__device__ float g_o[NP*C];         // gated attention output           32 MB

// round fp32 -> tf32 bit pattern (rna), returned as float bits
__device__ __forceinline__ float tf32r(float x) {
    uint32_t u;
    asm("cvt.rna.tf32.f32 %0, %1;" : "=r"(u) : "f"(x));
    return __uint_as_float(u);
}

// pack two floats into fp16x2 bits
__device__ __forceinline__ uint32_t f2h2(float x, float y) {
    __half2 h = __floats2half2_rn(x, y);
    return *(uint32_t*)&h;
}

__device__ __forceinline__ void mma_tf32(float& d0, float& d1, float& d2, float& d3,
                                         uint32_t a0, uint32_t a1, uint32_t a2, uint32_t a3,
                                         uint32_t b0, uint32_t b1) {
    asm volatile(
        "mma.sync.aligned.m16n8k8.row.col.f32.tf32.tf32.f32 "
        "{%0,%1,%2,%3}, {%4,%5,%6,%7}, {%8,%9}, {%0,%1,%2,%3};\n"
        : "+f"(d0), "+f"(d1), "+f"(d2), "+f"(d3)
        : "r"(a0), "r"(a1), "r"(a2), "r"(a3), "r"(b0), "r"(b1));
}

// fp16 MMA m16n8k16, fp32 accumulate
__device__ __forceinline__ void mma_f16(float& d0, float& d1, float& d2, float& d3,
                                        uint32_t a0, uint32_t a1, uint32_t a2, uint32_t a3,
                                        uint32_t b0, uint32_t b1) {
    asm volatile(
        "mma.sync.aligned.m16n8k16.row.col.f32.f16.f16.f32 "
        "{%0,%1,%2,%3}, {%4,%5,%6,%7}, {%8,%9}, {%0,%1,%2,%3};\n"
        : "+f"(d0), "+f"(d1), "+f"(d2), "+f"(d3)
        : "r"(a0), "r"(a1), "r"(a2), "r"(a3), "r"(b0), "r"(b1));
}

// ---------------------------------------------------------------------------
// Kernel 1: LayerNorm over C + triangle-bias projection ([h][q][k] layout).
// ---------------------------------------------------------------------------
__global__ void k_ln_tri(const float* __restrict__ x,
                         const float* __restrict__ ln_w,
                         const float* __restrict__ ln_b,
                         const float* __restrict__ w_tri) {
    __shared__ float swt[H*C];
    int tid = threadIdx.x;
    swt[tid]       = w_tri[tid];
    swt[tid + 256] = w_tri[tid + 256];
    __syncthreads();

    int warp = tid >> 5, lane = tid & 31;
    int pos = (blockIdx.x << 3) + warp;

    const float4 a = ((const float4*)(x + (size_t)pos * C))[lane];
    float s  = a.x + a.y + a.z + a.w;
    float s2 = a.x*a.x + a.y*a.y + a.z*a.z + a.w*a.w;
#pragma unroll
    for (int o = 16; o > 0; o >>= 1) {
        s  += __shfl_xor_sync(0xffffffffu, s,  o);
        s2 += __shfl_xor_sync(0xffffffffu, s2, o);
    }
    float mu   = s * (1.0f / C);
    float var  = s2 * (1.0f / C) - mu * mu;
    float rstd = rsqrtf(var + EPSV);

    float4 w = ((const float4*)ln_w)[lane];
    float4 b = ((const float4*)ln_b)[lane];
    float4 xn;
    xn.x = (a.x - mu) * rstd * w.x + b.x;
    xn.y = (a.y - mu) * rstd * w.y + b.y;
    xn.z = (a.z - mu) * rstd * w.z + b.z;
    xn.w = (a.w - mu) * rstd * w.w + b.w;
    float4 xr = {tf32r(xn.x), tf32r(xn.y), tf32r(xn.z), tf32r(xn.w)};
    ((float4*)(g_xn + (size_t)pos * C))[lane] = xr;

    // tri from UNROUNDED xn; packed 4-head reduction (6 shuffles)
    float t0, t1, t2, t3;
    {
        const float4 w0 = ((const float4*)(swt + 0 * C))[lane];
        const float4 w1 = ((const float4*)(swt + 1 * C))[lane];
        const float4 w2 = ((const float4*)(swt + 2 * C))[lane];
        const float4 w3 = ((const float4*)(swt + 3 * C))[lane];
        t0 = xn.x*w0.x + xn.y*w0.y + xn.z*w0.z + xn.w*w0.w;
        t1 = xn.x*w1.x + xn.y*w1.y + xn.z*w1.z + xn.w*w1.w;
        t2 = xn.x*w2.x + xn.y*w2.y + xn.z*w2.z + xn.w*w2.w;
        t3 = xn.x*w3.x + xn.y*w3.y + xn.z*w3.z + xn.w*w3.w;
    }
    bool o1 = lane & 1;
    float a01 = o1 ? t1 : t0;
    float b01 = o1 ? t0 : t1;
    a01 += __shfl_xor_sync(0xffffffffu, b01, 1);
    float a23 = o1 ? t3 : t2;
    float b23 = o1 ? t2 : t3;
    a23 += __shfl_xor_sync(0xffffffffu, b23, 1);
    bool o2 = lane & 2;
    float cc = o2 ? a23 : a01;
    float dd = o2 ? a01 : a23;
    cc += __shfl_xor_sync(0xffffffffu, dd, 2);
    cc += __shfl_xor_sync(0xffffffffu, cc, 4);
    cc += __shfl_xor_sync(0xffffffffu, cc, 8);
    cc += __shfl_xor_sync(0xffffffffu, cc, 16);

    if (lane < 4) {
        int q = pos >> 8, k = pos & 255;
        g_tri[((size_t)(lane * N + q)) * N + k] = cc;   // head = lane
    }
}

struct MmaAcc { float d[2][8][4]; };   // [mt][nt][reg]

// M-side streamed chunk (pitch 36), N-side resident (pitch 132, cbase offset)
__device__ __forceinline__ void mma_chunk_mres(const float (*Ac)[36], const float (*Br)[132],
                                               int cbase, int wm, int wn, int g, int tq,
                                               MmaAcc& A) {
#pragma unroll
    for (int ks = 0; ks < 32; ks += 8) {
        uint32_t af[2][4];
#pragma unroll
        for (int mt = 0; mt < 2; ++mt) {
            int r = wm * 32 + mt * 16;
            af[mt][0] = __float_as_uint(Ac[r + g][ks + tq]);
            af[mt][1] = __float_as_uint(Ac[r + g + 8][ks + tq]);
            af[mt][2] = __float_as_uint(Ac[r + g][ks + tq + 4]);
            af[mt][3] = __float_as_uint(Ac[r + g + 8][ks + tq + 4]);
        }
#pragma unroll
        for (int nt = 0; nt < 8; ++nt) {
            int cb = wn * 64 + nt * 8;
            uint32_t b0 = __float_as_uint(Br[cb + g][cbase + ks + tq]);
            uint32_t b1 = __float_as_uint(Br[cb + g][cbase + ks + tq + 4]);
#pragma unroll
            for (int mt = 0; mt < 2; ++mt)
                mma_tf32(A.d[mt][nt][0], A.d[mt][nt][1], A.d[mt][nt][2], A.d[mt][nt][3],
                         af[mt][0], af[mt][1], af[mt][2], af[mt][3], b0, b1);
        }
    }
}

// ---------------------------------------------------------------------------
// Kernel 2: fused K/V/Q/gate projection + fp16-MMA attention + gated epilogue.
// Block = (i, h), 256 threads (8 warps).
// ---------------------------------------------------------------------------
struct AttnSmem {
    union {
        struct {
            __half W4[128][136];  // stacked [k|v|q|g] head weights  34816 B
            __half Xs[32][136];   // xn chunk (fp16)                  8704 B
        } p;                      // 43520 B
        float T[QT][260];         // tri bias (fp32)                 66560 B
    } u;                          // 66560 B
    __half Ks[256][40];           // K (fp16), pitch 40h = 20 words  20480 B
    __half Qs[256][40];           // Q pre-scaled (fp16)             20480 B
    __half Vt[32][264];           // V transposed [d][key] (fp16)    16896 B
    __half P16[QT][264];          // softmax P (fp16)                33792 B
    float Gs[256][33];            // gate logits, raw fp32           33792 B
    float mb[256];                //  1024 B
    float rmax[QT][4];            //  1024 B
    float rsum[QT][4];            //  1024 B
};                                // 195072 B

__global__ void __launch_bounds__(256)
k_attn(const float* __restrict__ mask,
       const float* __restrict__ wq, const float* __restrict__ wk,
       const float* __restrict__ wv, const float* __restrict__ wg,
       const float* __restrict__ bg) {
    extern __shared__ char smraw[];
    AttnSmem* sm = (AttnSmem*)smraw;

    int i = blockIdx.x, h = blockIdx.y;
    int tid = threadIdx.x, w = tid >> 5, lane = tid & 31;
    int g = lane >> 2, tq = lane & 3;
    const float sc = 0.17677669529663688f;  // 1/sqrt(32)

    // ===================== Phase 1: project K/V/Q/gate (fp16 MMA) ==========
    // W4 rows: 0-31 Wk_h, 32-63 Wv_h, 64-95 Wq_h, 96-127 Wg slice [h*32, +32)
    {
        int pwm = w >> 2, pwn = w & 3;    // 2 warps M(32), 4 warps N(128)
#pragma unroll
        for (int t = 0; t < 16; ++t) {
            int idx = tid + t * 256;      // 0..4095
            int row = idx >> 5, j4 = idx & 31;
            const float* src = (row < 32) ? wk : (row < 64) ? wv : (row < 96) ? wq : wg;
            float4 b = *(const float4*)&src[(size_t)(h * 32 + (row & 31)) * C + j4 * 4];
            *(uint2*)&sm->u.p.W4[row][j4 * 4] = make_uint2(f2h2(b.x, b.y), f2h2(b.z, b.w));
        }
        sm->mb[tid] = INFV * (mask[i * N + tid] - 1.0f);

        // stage xn chunk 0 (32 rows)
        float4 xpre[4];
#pragma unroll
        for (int t = 0; t < 4; ++t) {
            int idx = tid + t * 256;      // 0..1023
            int row = idx >> 5, j4 = idx & 31;
            xpre[t] = *(const float4*)&g_xn[((size_t)(i * N + row)) * C + j4 * 4];
        }
#pragma unroll
        for (int t = 0; t < 4; ++t) {
            int idx = tid + t * 256;
            int row = idx >> 5, j4 = idx & 31;
            *(uint2*)&sm->u.p.Xs[row][j4 * 4] =
                make_uint2(f2h2(xpre[t].x, xpre[t].y), f2h2(xpre[t].z, xpre[t].w));
        }
        __syncthreads();

        for (int c = 0; c < 8; ++c) {
            if (c < 7) {
#pragma unroll
                for (int t = 0; t < 4; ++t) {
                    int idx = tid + t * 256;
                    int row = idx >> 5, j4 = idx & 31;
                    xpre[t] = *(const float4*)&g_xn[((size_t)(i * N + (c + 1) * 32 + row)) * C + j4 * 4];
                }
            }
            // GEMM: M=32, N=128, K=128. fp16 m16n8k16, 8 k-steps.
            float pacc[4][4] = {};
#pragma unroll
            for (int ks = 0; ks < 128; ks += 16) {
                int r = pwm * 16;
                uint32_t a0 = *(const uint32_t*)&sm->u.p.Xs[r + g][ks + 2 * tq];
                uint32_t a1 = *(const uint32_t*)&sm->u.p.Xs[r + g + 8][ks + 2 * tq];
                uint32_t a2 = *(const uint32_t*)&sm->u.p.Xs[r + g][ks + 2 * tq + 8];
                uint32_t a3 = *(const uint32_t*)&sm->u.p.Xs[r + g + 8][ks + 2 * tq + 8];
#pragma unroll
                for (int nt = 0; nt < 4; ++nt) {
                    int cb = pwn * 32 + nt * 8;
                    uint32_t b0 = *(const uint32_t*)&sm->u.p.W4[cb + g][ks + 2 * tq];
                    uint32_t b1 = *(const uint32_t*)&sm->u.p.W4[cb + g][ks + 2 * tq + 8];
                    mma_f16(pacc[nt][0], pacc[nt][1], pacc[nt][2], pacc[nt][3],
                            a0, a1, a2, a3, b0, b1);
                }
            }
            // scatter: pwn -> 0=K, 1=V(transposed), 2=Q(scaled), 3=gate(fp32)
            {
                int row0 = c * 32 + pwm * 16 + g;
#pragma unroll
                for (int nt = 0; nt < 4; ++nt) {
                    int off = nt * 8 + 2 * tq;
                    float m0 = pacc[nt][0], m1 = pacc[nt][1];
                    float m2 = pacc[nt][2], m3 = pacc[nt][3];
                    if (pwn == 3) {
                        sm->Gs[row0][off]         = m0;
                        sm->Gs[row0][off + 1]     = m1;
                        sm->Gs[row0 + 8][off]     = m2;
                        sm->Gs[row0 + 8][off + 1] = m3;
                    } else if (pwn == 1) {
                        sm->Vt[off][row0]         = __float2half_rn(m0);
                        sm->Vt[off + 1][row0]     = __float2half_rn(m1);
                        sm->Vt[off][row0 + 8]     = __float2half_rn(m2);
                        sm->Vt[off + 1][row0 + 8] = __float2half_rn(m3);
                    } else {
                        if (pwn == 2) { m0 *= sc; m1 *= sc; m2 *= sc; m3 *= sc; }
                        __half* dst = (pwn == 0) ? &sm->Ks[0][0] : &sm->Qs[0][0];
                        *(uint32_t*)&dst[row0 * 40 + off]       = f2h2(m0, m1);
                        *(uint32_t*)&dst[(row0 + 8) * 40 + off] = f2h2(m2, m3);
                    }
                }
            }
            if (c < 7) {
                __syncthreads();
#pragma unroll
                for (int t = 0; t < 4; ++t) {
                    int idx = tid + t * 256;
                    int row = idx >> 5, j4 = idx & 31;
                    *(uint2*)&sm->u.p.Xs[row][j4 * 4] =
                        make_uint2(f2h2(xpre[t].x, xpre[t].y), f2h2(xpre[t].z, xpre[t].w));
                }
                __syncthreads();
            }
        }
    }

    // ===================== Phase 2: attention =====================
    int wm = w >> 2, wn = w & 3;          // 2 warps along M(64), 4 along N(256)

    for (int qt = 0; qt < 4; ++qt) {
        int q0 = qt * QT;
        __syncthreads();   // phase1 / previous-qt PV done

        // ---- load tri tile [q0..q0+63][0..255] into T (fp32) ----
#pragma unroll
        for (int t = 0; t < 16; ++t) {
            int idx = tid + t * 256;           // 0..4095
            int row = idx >> 6, k4 = idx & 63;
            float4 tv = *(const float4*)&g_tri[((size_t)(h * N + q0 + row)) * N + k4 * 4];
            *(float4*)&sm->u.T[row][k4 * 4] = tv;
        }
        __syncthreads();

        // ---- S = Q K^T : fp16 m16n8k16, 2 k-steps, 2mt x 8nt ----
        float sacc[2][8][4];
#pragma unroll
        for (int mt = 0; mt < 2; ++mt)
#pragma unroll
            for (int nt = 0; nt < 8; ++nt)
#pragma unroll
                for (int r = 0; r < 4; ++r) sacc[mt][nt][r] = 0.0f;

#pragma unroll
        for (int ks = 0; ks < 32; ks += 16) {
            uint32_t af[2][4];
#pragma unroll
            for (int mt = 0; mt < 2; ++mt) {
                int r = q0 + wm * 32 + mt * 16;
                af[mt][0] = *(const uint32_t*)&sm->Qs[r + g][ks + 2 * tq];
                af[mt][1] = *(const uint32_t*)&sm->Qs[r + g + 8][ks + 2 * tq];
                af[mt][2] = *(const uint32_t*)&sm->Qs[r + g][ks + 2 * tq + 8];
                af[mt][3] = *(const uint32_t*)&sm->Qs[r + g + 8][ks + 2 * tq + 8];
            }
#pragma unroll
            for (int nt = 0; nt < 8; ++nt) {
                int cb = wn * 64 + nt * 8;
                uint32_t b0 = *(const uint32_t*)&sm->Ks[cb + g][ks + 2 * tq];
                uint32_t b1 = *(const uint32_t*)&sm->Ks[cb + g][ks + 2 * tq + 8];
#pragma unroll
                for (int mt = 0; mt < 2; ++mt)
                    mma_f16(sacc[mt][nt][0], sacc[mt][nt][1], sacc[mt][nt][2], sacc[mt][nt][3],
                            af[mt][0], af[mt][1], af[mt][2], af[mt][3], b0, b1);
            }
        }

        // ---- add tri + mask bias; partial row max ----
        float pmax[2][2];
        pmax[0][0] = pmax[0][1] = pmax[1][0] = pmax[1][1] = -3.4e38f;
#pragma unroll
        for (int mt = 0; mt < 2; ++mt) {
            int r0 = wm * 32 + mt * 16 + g;
#pragma unroll
            for (int nt = 0; nt < 8; ++nt) {
                int c0 = wn * 64 + nt * 8 + 2 * tq;
                float m0v = sm->mb[c0], m1v = sm->mb[c0 + 1];
                sacc[mt][nt][0] += sm->u.T[r0][c0]     + m0v;
                sacc[mt][nt][1] += sm->u.T[r0][c0 + 1] + m1v;
                sacc[mt][nt][2] += sm->u.T[r0 + 8][c0]     + m0v;
                sacc[mt][nt][3] += sm->u.T[r0 + 8][c0 + 1] + m1v;
                pmax[mt][0] = fmaxf(pmax[mt][0], fmaxf(sacc[mt][nt][0], sacc[mt][nt][1]));
                pmax[mt][1] = fmaxf(pmax[mt][1], fmaxf(sacc[mt][nt][2], sacc[mt][nt][3]));
            }
        }
#pragma unroll
        for (int mt = 0; mt < 2; ++mt)
#pragma unroll
            for (int rh = 0; rh < 2; ++rh) {
                float v = pmax[mt][rh];
                v = fmaxf(v, __shfl_xor_sync(0xffffffffu, v, 1));
                v = fmaxf(v, __shfl_xor_sync(0xffffffffu, v, 2));
                pmax[mt][rh] = v;
            }
        if (tq == 0) {
#pragma unroll
            for (int mt = 0; mt < 2; ++mt) {
                int r0 = wm * 32 + mt * 16 + g;
                sm->rmax[r0][wn]     = pmax[mt][0];
                sm->rmax[r0 + 8][wn] = pmax[mt][1];
            }
        }
        __syncthreads();

        // ---- exp + write P (fp16) + partial row sums ----
        float psum[2][2] = {{0.0f, 0.0f}, {0.0f, 0.0f}};
#pragma unroll
        for (int mt = 0; mt < 2; ++mt) {
            int r0 = wm * 32 + mt * 16 + g;
            float4 m4a = *(float4*)sm->rmax[r0];
            float rm0 = fmaxf(fmaxf(m4a.x, m4a.y), fmaxf(m4a.z, m4a.w));
            float4 m4b = *(float4*)sm->rmax[r0 + 8];
            float rm1 = fmaxf(fmaxf(m4b.x, m4b.y), fmaxf(m4b.z, m4b.w));
#pragma unroll
            for (int nt = 0; nt < 8; ++nt) {
                int c0 = wn * 64 + nt * 8 + 2 * tq;
                __half2 hp0 = __floats2half2_rn(__expf(sacc[mt][nt][0] - rm0),
                                                __expf(sacc[mt][nt][1] - rm0));
                __half2 hp1 = __floats2half2_rn(__expf(sacc[mt][nt][2] - rm1),
                                                __expf(sacc[mt][nt][3] - rm1));
                *(__half2*)&sm->P16[r0][c0]     = hp0;
                *(__half2*)&sm->P16[r0 + 8][c0] = hp1;
                float2 p0f = __half22float2(hp0);
                float2 p1f = __half22float2(hp1);
                psum[mt][0] += p0f.x + p0f.y;
                psum[mt][1] += p1f.x + p1f.y;
            }
        }
#pragma unroll
        for (int mt = 0; mt < 2; ++mt)
#pragma unroll
            for (int rh = 0; rh < 2; ++rh) {
                float v = psum[mt][rh];
                v += __shfl_xor_sync(0xffffffffu, v, 1);
                v += __shfl_xor_sync(0xffffffffu, v, 2);
                psum[mt][rh] = v;
            }
        if (tq == 0) {
#pragma unroll
            for (int mt = 0; mt < 2; ++mt) {
                int r0 = wm * 32 + mt * 16 + g;
                sm->rsum[r0][wn]     = psum[mt][0];
                sm->rsum[r0 + 8][wn] = psum[mt][1];
            }
        }
        __syncthreads();

        // ---- O = P V : fp16 m16n8k16, 16 k-steps, warp tile 32x8 ----
        int nb = wn * 8;
        float oacc[2][4] = {{0,0,0,0},{0,0,0,0}};
#pragma unroll
        for (int ks16 = 0; ks16 < 16; ++ks16) {
            int kk = ks16 * 16;
            uint32_t b0 = *(const uint32_t*)&sm->Vt[nb + g][kk + 2 * tq];
            uint32_t b1 = *(const uint32_t*)&sm->Vt[nb + g][kk + 2 * tq + 8];
#pragma unroll
            for (int mt = 0; mt < 2; ++mt) {
                int r0 = wm * 32 + mt * 16 + g;
                uint32_t a0 = *(const uint32_t*)&sm->P16[r0][kk + 2 * tq];
                uint32_t a1 = *(const uint32_t*)&sm->P16[r0 + 8][kk + 2 * tq];
                uint32_t a2 = *(const uint32_t*)&sm->P16[r0][kk + 2 * tq + 8];
                uint32_t a3 = *(const uint32_t*)&sm->P16[r0 + 8][kk + 2 * tq + 8];
                mma_f16(oacc[mt][0], oacc[mt][1], oacc[mt][2], oacc[mt][3],
                        a0, a1, a2, a3, b0, b1);
            }
        }

        // ---- epilogue: normalize, apply sigmoid gate, store gated output ----
#pragma unroll
        for (int mt = 0; mt < 2; ++mt) {
            int r0 = wm * 32 + mt * 16 + g;
            float4 s0 = *(float4*)sm->rsum[r0];
            float inv0 = 1.0f / (s0.x + s0.y + s0.z + s0.w);
            float4 s1 = *(float4*)sm->rsum[r0 + 8];
            float inv1 = 1.0f / (s1.x + s1.y + s1.z + s1.w);
            int col = nb + 2 * tq;
            float bga = bg[h * 32 + col], bgb = bg[h * 32 + col + 1];
            int gr0 = q0 + r0, gr1 = q0 + r0 + 8;
            float d00 = 1.0f + __expf(-(sm->Gs[gr0][col]     + bga));
            float d01 = 1.0f + __expf(-(sm->Gs[gr0][col + 1] + bgb));
            float d10 = 1.0f + __expf(-(sm->Gs[gr1][col]     + bga));
            float d11 = 1.0f + __expf(-(sm->Gs[gr1][col + 1] + bgb));
            size_t b0a = ((size_t)(i * N + gr0)) * C + h * D + col;
            *(float2*)&g_o[b0a] = make_float2((oacc[mt][0] * inv0) / d00,
                                              (oacc[mt][1] * inv0) / d01);
            size_t b1a = ((size_t)(i * N + gr1)) * C + h * D + col;
            *(float2*)&g_o[b1a] = make_float2((oacc[mt][2] * inv1) / d10,
                                              (oacc[mt][3] * inv1) / d11);
        }
    }
}

// ---------------------------------------------------------------------------
// Kernel 3: output projection. grid=NP/128, 2 blocks/SM.
// ---------------------------------------------------------------------------
struct OutSmem {
    float Bs[128][132];     // resident wo        67584 B
    float As[2][128][36];   // A chunks           36864 B
};                          // 104448 B

__global__ void __launch_bounds__(256, 2)
k_out(const float* __restrict__ wo, const float* __restrict__ bo,
      float* __restrict__ out) {
    extern __shared__ char smraw[];
    OutSmem* sm = (OutSmem*)smraw;
    int tid = threadIdx.x;
    int m0 = blockIdx.x * 128;
    int w = tid >> 5, lane = tid & 31;
    int wm = w >> 1, wn = w & 1;
    int g = lane >> 2, tq = lane & 3;

#pragma unroll
    for (int t = 0; t < 16; ++t) {
        int idx = tid + t * 256;
        int row = idx >> 5, j4 = idx & 31;
        float4 b = *(const float4*)&wo[(size_t)row * C + j4 * 4];
        float4 r = {tf32r(b.x), tf32r(b.y), tf32r(b.z), tf32r(b.w)};
        *(float4*)&sm->Bs[row][j4 * 4] = r;
    }
#pragma unroll
    for (int t = 0; t < 4; ++t) {
        int idx = tid + t * 256;
        int row = idx >> 3, j = idx & 7;
        float4 ov = *(const float4*)&g_o[(size_t)(m0 + row) * C + j * 4];
        float4 r = {tf32r(ov.x), tf32r(ov.y), tf32r(ov.z), tf32r(ov.w)};
        *(float4*)&sm->As[0][row][j * 4] = r;
    }
    __syncthreads();

    MmaAcc acc;
#pragma unroll
    for (int mt = 0; mt < 2; ++mt)
#pragma unroll
        for (int nt = 0; nt < 8; ++nt)
#pragma unroll
            for (int r = 0; r < 4; ++r) acc.d[mt][nt][r] = 0.0f;

    for (int kc = 0; kc < 4; ++kc) {
        float4 po[4];
        if (kc < 3) {
#pragma unroll
            for (int t = 0; t < 4; ++t) {
                int idx = tid + t * 256;
                int row = idx >> 3, j = idx & 7;
                po[t] = *(const float4*)&g_o[(size_t)(m0 + row) * C + (kc + 1) * 32 + j * 4];
            }
        }
        mma_chunk_mres(sm->As[kc & 1], sm->Bs, kc * 32, wm, wn, g, tq, acc);
        if (kc < 3) {
#pragma unroll
            for (int t = 0; t < 4; ++t) {
                int idx = tid + t * 256;
                int row = idx >> 3, j = idx & 7;
                float4 r = {tf32r(po[t].x), tf32r(po[t].y), tf32r(po[t].z), tf32r(po[t].w)};
                *(float4*)&sm->As[(kc + 1) & 1][row][j * 4] = r;
            }
            __syncthreads();
        }
    }

#pragma unroll
    for (int mt = 0; mt < 2; ++mt) {
        int r0 = m0 + wm * 32 + mt * 16 + g;
#pragma unroll
        for (int nt = 0; nt < 8; ++nt) {
            int cb = wn * 64 + nt * 8 + 2 * tq;
            float2 bov = *(const float2*)&bo[cb];
            *(float2*)&out[(size_t)r0 * C + cb] =
                make_float2(acc.d[mt][nt][0] + bov.x, acc.d[mt][nt][1] + bov.y);
            *(float2*)&out[(size_t)(r0 + 8) * C + cb] =
                make_float2(acc.d[mt][nt][2] + bov.x, acc.d[mt][nt][3] + bov.y);
        }
    }
}

// ---------------------------------------------------------------------------
extern "C" void kernel_launch(void* const* d_in, const int* in_sizes, int n_in,
                              void* d_out, int out_size) {
    const float* x     = (const float*)d_in[0];
    const float* mask  = (const float*)d_in[1];
    const float* ln_w  = (const float*)d_in[2];
    const float* ln_b  = (const float*)d_in[3];
    const float* w_tri = (const float*)d_in[4];
    const float* wq    = (const float*)d_in[5];
    const float* wk    = (const float*)d_in[6];
    const float* wv    = (const float*)d_in[7];
    const float* wg    = (const float*)d_in[8];
    const float* bg    = (const float*)d_in[9];
    const float* wo    = (const float*)d_in[10];
    const float* bo    = (const float*)d_in[11];
    float* out = (float*)d_out;

    (void)in_sizes; (void)n_in; (void)out_size;

    cudaFuncSetAttribute(k_out, cudaFuncAttributeMaxDynamicSharedMemorySize,
                         (int)sizeof(OutSmem));
    cudaFuncSetAttribute(k_attn, cudaFuncAttributeMaxDynamicSharedMemorySize,
                         (int)sizeof(AttnSmem));

    k_ln_tri<<<NP / 8, 256>>>(x, ln_w, ln_b, w_tri);
    k_attn<<<dim3(N, H), 256, sizeof(AttnSmem)>>>(mask, wq, wk, wv, wg, bg);
    k_out<<<NP / 128, 256, sizeof(OutSmem)>>>(wo, bo, out);
}

// round 16
// speedup vs baseline: 1.5010x; 1.0659x over previous
#include <cuda_runtime.h>
#include <cuda_fp16.h>
#include <math.h>
#include <stdint.h>

#define N 256
#define C 128
#define H 4
#define D 32
#define NP (N*N)            // 65536 positions
#define EPSV 1e-5f
#define INFV 1000000000.0f
#define QT 64               // attention query tile

// Scratch (static device arrays; no allocation in kernel_launch)
__device__ __half g_xn[NP*C];       // layernormed x, fp16   16 MB
__device__ float  g_tri[H*N*N];     // tri bias [h][q][k]     1 MB
__device__ __half g_o[NP*C];        // gated attn output     16 MB

__device__ __forceinline__ uint32_t f2h2(float x, float y) {
    __half2 h = __floats2half2_rn(x, y);
    return *(uint32_t*)&h;
}

// fp16 MMA m16n8k16, fp32 accumulate
__device__ __forceinline__ void mma_f16(float& d0, float& d1, float& d2, float& d3,
                                        uint32_t a0, uint32_t a1, uint32_t a2, uint32_t a3,
                                        uint32_t b0, uint32_t b1) {
    asm volatile(
        "mma.sync.aligned.m16n8k16.row.col.f32.f16.f16.f32 "
        "{%0,%1,%2,%3}, {%4,%5,%6,%7}, {%8,%9}, {%0,%1,%2,%3};\n"
        : "+f"(d0), "+f"(d1), "+f"(d2), "+f"(d3)
        : "r"(a0), "r"(a1), "r"(a2), "r"(a3), "r"(b0), "r"(b1));
}

// ---------------------------------------------------------------------------
// Kernel 1: LayerNorm over C + triangle-bias projection ([h][q][k] layout).
// g_xn stored fp16; tri computed from unrounded fp32 values.
// ---------------------------------------------------------------------------
__global__ void k_ln_tri(const float* __restrict__ x,
                         const float* __restrict__ ln_w,
                         const float* __restrict__ ln_b,
                         const float* __restrict__ w_tri) {
    __shared__ float swt[H*C];
    int tid = threadIdx.x;
    swt[tid]       = w_tri[tid];
    swt[tid + 256] = w_tri[tid + 256];
    __syncthreads();

    int warp = tid >> 5, lane = tid & 31;
    int pos = (blockIdx.x << 3) + warp;

    const float4 a = ((const float4*)(x + (size_t)pos * C))[lane];
    float s  = a.x + a.y + a.z + a.w;
    float s2 = a.x*a.x + a.y*a.y + a.z*a.z + a.w*a.w;
#pragma unroll
    for (int o = 16; o > 0; o >>= 1) {
        s  += __shfl_xor_sync(0xffffffffu, s,  o);
        s2 += __shfl_xor_sync(0xffffffffu, s2, o);
    }
    float mu   = s * (1.0f / C);
    float var  = s2 * (1.0f / C) - mu * mu;
    float rstd = rsqrtf(var + EPSV);

    float4 w = ((const float4*)ln_w)[lane];
    float4 b = ((const float4*)ln_b)[lane];
    float4 xn;
    xn.x = (a.x - mu) * rstd * w.x + b.x;
    xn.y = (a.y - mu) * rstd * w.y + b.y;
    xn.z = (a.z - mu) * rstd * w.z + b.z;
    xn.w = (a.w - mu) * rstd * w.w + b.w;
    ((uint2*)(g_xn + (size_t)pos * C))[lane] =
        make_uint2(f2h2(xn.x, xn.y), f2h2(xn.z, xn.w));

    // tri from fp32 xn; packed 4-head reduction (6 shuffles)
    float t0, t1, t2, t3;
    {
        const float4 w0 = ((const float4*)(swt + 0 * C))[lane];
        const float4 w1 = ((const float4*)(swt + 1 * C))[lane];
        const float4 w2 = ((const float4*)(swt + 2 * C))[lane];
        const float4 w3 = ((const float4*)(swt + 3 * C))[lane];
        t0 = xn.x*w0.x + xn.y*w0.y + xn.z*w0.z + xn.w*w0.w;
        t1 = xn.x*w1.x + xn.y*w1.y + xn.z*w1.z + xn.w*w1.w;
        t2 = xn.x*w2.x + xn.y*w2.y + xn.z*w2.z + xn.w*w2.w;
        t3 = xn.x*w3.x + xn.y*w3.y + xn.z*w3.z + xn.w*w3.w;
    }
    bool o1 = lane & 1;
    float a01 = o1 ? t1 : t0;
    float b01 = o1 ? t0 : t1;
    a01 += __shfl_xor_sync(0xffffffffu, b01, 1);
    float a23 = o1 ? t3 : t2;
    float b23 = o1 ? t2 : t3;
    a23 += __shfl_xor_sync(0xffffffffu, b23, 1);
    bool o2 = lane & 2;
    float cc = o2 ? a23 : a01;
    float dd = o2 ? a01 : a23;
    cc += __shfl_xor_sync(0xffffffffu, dd, 2);
    cc += __shfl_xor_sync(0xffffffffu, cc, 4);
    cc += __shfl_xor_sync(0xffffffffu, cc, 8);
    cc += __shfl_xor_sync(0xffffffffu, cc, 16);

    if (lane < 4) {
        int q = pos >> 8, k = pos & 255;
        g_tri[((size_t)(lane * N + q)) * N + k] = cc;   // head = lane
    }
}

// ---------------------------------------------------------------------------
// Kernel 2: fused K/V/Q/gate projection + fp16-MMA attention + gated epilogue.
// Block = (i, h), 256 threads (8 warps).
// ---------------------------------------------------------------------------
struct AttnSmem {
    union {
        struct {
            __half W4[128][136];  // stacked [k|v|q|g] head weights  34816 B
            __half Xs[32][136];   // xn chunk (fp16)                  8704 B
        } p;                      // 43520 B
        float T[QT][260];         // tri bias (fp32)                 66560 B
    } u;                          // 66560 B
    __half Ks[256][40];           // K (fp16), pitch 40h = 20 words  20480 B
    __half Qs[256][40];           // Q pre-scaled (fp16)             20480 B
    __half Vt[32][264];           // V transposed [d][key] (fp16)    16896 B
    __half P16[QT][264];          // softmax P (fp16)                33792 B
    float Gs[256][33];            // gate logits, raw fp32           33792 B
    float mb[256];                //  1024 B
    float rmax[QT][4];            //  1024 B
    float rsum[QT][4];            //  1024 B
};                                // 195072 B

__global__ void __launch_bounds__(256)
k_attn(const float* __restrict__ mask,
       const float* __restrict__ wq, const float* __restrict__ wk,
       const float* __restrict__ wv, const float* __restrict__ wg,
       const float* __restrict__ bg) {
    extern __shared__ char smraw[];
    AttnSmem* sm = (AttnSmem*)smraw;

    int i = blockIdx.x, h = blockIdx.y;
    int tid = threadIdx.x, w = tid >> 5, lane = tid & 31;
    int g = lane >> 2, tq = lane & 3;
    const float sc = 0.17677669529663688f;  // 1/sqrt(32)

    // ===================== Phase 1: project K/V/Q/gate (fp16 MMA) ==========
    // W4 rows: 0-31 Wk_h, 32-63 Wv_h, 64-95 Wq_h, 96-127 Wg slice [h*32, +32)
    {
        int pwm = w >> 2, pwn = w & 3;    // 2 warps M(32), 4 warps N(128)
#pragma unroll
        for (int t = 0; t < 16; ++t) {
            int idx = tid + t * 256;      // 0..4095
            int row = idx >> 5, j4 = idx & 31;
            const float* src = (row < 32) ? wk : (row < 64) ? wv : (row < 96) ? wq : wg;
            float4 b = *(const float4*)&src[(size_t)(h * 32 + (row & 31)) * C + j4 * 4];
            *(uint2*)&sm->u.p.W4[row][j4 * 4] = make_uint2(f2h2(b.x, b.y), f2h2(b.z, b.w));
        }
        sm->mb[tid] = INFV * (mask[i * N + tid] - 1.0f);

        const __half* Xg = g_xn + (size_t)(i * N) * C;
        // stage xn chunk 0 (32 rows) — pure bit copy
        uint4 xpre[2];
#pragma unroll
        for (int t = 0; t < 2; ++t) {
            int idx = tid + t * 256;      // 0..511
            int row = idx >> 4, j8 = idx & 15;
            xpre[t] = *(const uint4*)&Xg[(size_t)row * C + j8 * 8];
        }
#pragma unroll
        for (int t = 0; t < 2; ++t) {
            int idx = tid + t * 256;
            int row = idx >> 4, j8 = idx & 15;
            *(uint4*)&sm->u.p.Xs[row][j8 * 8] = xpre[t];
        }
        __syncthreads();

        for (int c = 0; c < 8; ++c) {
            if (c < 7) {
#pragma unroll
                for (int t = 0; t < 2; ++t) {
                    int idx = tid + t * 256;
                    int row = idx >> 4, j8 = idx & 15;
                    xpre[t] = *(const uint4*)&Xg[(size_t)((c + 1) * 32 + row) * C + j8 * 8];
                }
            }
            // GEMM: M=32, N=128, K=128. fp16 m16n8k16, 8 k-steps.
            float pacc[4][4] = {};
#pragma unroll
            for (int ks = 0; ks < 128; ks += 16) {
                int r = pwm * 16;
                uint32_t a0 = *(const uint32_t*)&sm->u.p.Xs[r + g][ks + 2 * tq];
                uint32_t a1 = *(const uint32_t*)&sm->u.p.Xs[r + g + 8][ks + 2 * tq];
                uint32_t a2 = *(const uint32_t*)&sm->u.p.Xs[r + g][ks + 2 * tq + 8];
                uint32_t a3 = *(const uint32_t*)&sm->u.p.Xs[r + g + 8][ks + 2 * tq + 8];
#pragma unroll
                for (int nt = 0; nt < 4; ++nt) {
                    int cb = pwn * 32 + nt * 8;
                    uint32_t b0 = *(const uint32_t*)&sm->u.p.W4[cb + g][ks + 2 * tq];
                    uint32_t b1 = *(const uint32_t*)&sm->u.p.W4[cb + g][ks + 2 * tq + 8];
                    mma_f16(pacc[nt][0], pacc[nt][1], pacc[nt][2], pacc[nt][3],
                            a0, a1, a2, a3, b0, b1);
                }
            }
            // scatter: pwn -> 0=K, 1=V(transposed), 2=Q(scaled), 3=gate(fp32)
            {
                int row0 = c * 32 + pwm * 16 + g;
#pragma unroll
                for (int nt = 0; nt < 4; ++nt) {
                    int off = nt * 8 + 2 * tq;
                    float m0 = pacc[nt][0], m1 = pacc[nt][1];
                    float m2 = pacc[nt][2], m3 = pacc[nt][3];
                    if (pwn == 3) {
                        sm->Gs[row0][off]         = m0;
                        sm->Gs[row0][off + 1]     = m1;
                        sm->Gs[row0 + 8][off]     = m2;
                        sm->Gs[row0 + 8][off + 1] = m3;
                    } else if (pwn == 1) {
                        sm->Vt[off][row0]         = __float2half_rn(m0);
                        sm->Vt[off + 1][row0]     = __float2half_rn(m1);
                        sm->Vt[off][row0 + 8]     = __float2half_rn(m2);
                        sm->Vt[off + 1][row0 + 8] = __float2half_rn(m3);
                    } else {
                        if (pwn == 2) { m0 *= sc; m1 *= sc; m2 *= sc; m3 *= sc; }
                        __half* dst = (pwn == 0) ? &sm->Ks[0][0] : &sm->Qs[0][0];
                        *(uint32_t*)&dst[row0 * 40 + off]       = f2h2(m0, m1);
                        *(uint32_t*)&dst[(row0 + 8) * 40 + off] = f2h2(m2, m3);
                    }
                }
            }
            if (c < 7) {
                __syncthreads();
#pragma unroll
                for (int t = 0; t < 2; ++t) {
                    int idx = tid + t * 256;
                    int row = idx >> 4, j8 = idx & 15;
                    *(uint4*)&sm->u.p.Xs[row][j8 * 8] = xpre[t];
                }
                __syncthreads();
            }
        }
    }

    // ===================== Phase 2: attention =====================
    int wm = w >> 2, wn = w & 3;          // 2 warps along M(64), 4 along N(256)

    for (int qt = 0; qt < 4; ++qt) {
        int q0 = qt * QT;
        __syncthreads();   // phase1 / previous-qt PV done

        // ---- load tri tile [q0..q0+63][0..255] into T (fp32) ----
#pragma unroll
        for (int t = 0; t < 16; ++t) {
            int idx = tid + t * 256;           // 0..4095
            int row = idx >> 6, k4 = idx & 63;
            float4 tv = *(const float4*)&g_tri[((size_t)(h * N + q0 + row)) * N + k4 * 4];
            *(float4*)&sm->u.T[row][k4 * 4] = tv;
        }
        __syncthreads();

        // ---- S = Q K^T : fp16 m16n8k16, 2 k-steps, 2mt x 8nt ----
        float sacc[2][8][4];
#pragma unroll
        for (int mt = 0; mt < 2; ++mt)
#pragma unroll
            for (int nt = 0; nt < 8; ++nt)
#pragma unroll
                for (int r = 0; r < 4; ++r) sacc[mt][nt][r] = 0.0f;

#pragma unroll
        for (int ks = 0; ks < 32; ks += 16) {
            uint32_t af[2][4];
#pragma unroll
            for (int mt = 0; mt < 2; ++mt) {
                int r = q0 + wm * 32 + mt * 16;
                af[mt][0] = *(const uint32_t*)&sm->Qs[r + g][ks + 2 * tq];
                af[mt][1] = *(const uint32_t*)&sm->Qs[r + g + 8][ks + 2 * tq];
                af[mt][2] = *(const uint32_t*)&sm->Qs[r + g][ks + 2 * tq + 8];
                af[mt][3] = *(const uint32_t*)&sm->Qs[r + g + 8][ks + 2 * tq + 8];
            }
#pragma unroll
            for (int nt = 0; nt < 8; ++nt) {
                int cb = wn * 64 + nt * 8;
                uint32_t b0 = *(const uint32_t*)&sm->Ks[cb + g][ks + 2 * tq];
                uint32_t b1 = *(const uint32_t*)&sm->Ks[cb + g][ks + 2 * tq + 8];
#pragma unroll
                for (int mt = 0; mt < 2; ++mt)
                    mma_f16(sacc[mt][nt][0], sacc[mt][nt][1], sacc[mt][nt][2], sacc[mt][nt][3],
                            af[mt][0], af[mt][1], af[mt][2], af[mt][3], b0, b1);
            }
        }

        // ---- add tri + mask bias; partial row max ----
        float pmax[2][2];
        pmax[0][0] = pmax[0][1] = pmax[1][0] = pmax[1][1] = -3.4e38f;
#pragma unroll
        for (int mt = 0; mt < 2; ++mt) {
            int r0 = wm * 32 + mt * 16 + g;
#pragma unroll
            for (int nt = 0; nt < 8; ++nt) {
                int c0 = wn * 64 + nt * 8 + 2 * tq;
                float m0v = sm->mb[c0], m1v = sm->mb[c0 + 1];
                sacc[mt][nt][0] += sm->u.T[r0][c0]     + m0v;
                sacc[mt][nt][1] += sm->u.T[r0][c0 + 1] + m1v;
                sacc[mt][nt][2] += sm->u.T[r0 + 8][c0]     + m0v;
                sacc[mt][nt][3] += sm->u.T[r0 + 8][c0 + 1] + m1v;
                pmax[mt][0] = fmaxf(pmax[mt][0], fmaxf(sacc[mt][nt][0], sacc[mt][nt][1]));
                pmax[mt][1] = fmaxf(pmax[mt][1], fmaxf(sacc[mt][nt][2], sacc[mt][nt][3]));
            }
        }
#pragma unroll
        for (int mt = 0; mt < 2; ++mt)
#pragma unroll
            for (int rh = 0; rh < 2; ++rh) {
                float v = pmax[mt][rh];
                v = fmaxf(v, __shfl_xor_sync(0xffffffffu, v, 1));
                v = fmaxf(v, __shfl_xor_sync(0xffffffffu, v, 2));
                pmax[mt][rh] = v;
            }
        if (tq == 0) {
#pragma unroll
            for (int mt = 0; mt < 2; ++mt) {
                int r0 = wm * 32 + mt * 16 + g;
                sm->rmax[r0][wn]     = pmax[mt][0];
                sm->rmax[r0 + 8][wn] = pmax[mt][1];
            }
        }
        __syncthreads();

        // ---- exp + write P (fp16) + partial row sums ----
        float psum[2][2] = {{0.0f, 0.0f}, {0.0f, 0.0f}};
#pragma unroll
        for (int mt = 0; mt < 2; ++mt) {
            int r0 = wm * 32 + mt * 16 + g;
            float4 m4a = *(float4*)sm->rmax[r0];
            float rm0 = fmaxf(fmaxf(m4a.x, m4a.y), fmaxf(m4a.z, m4a.w));
            float4 m4b = *(float4*)sm->rmax[r0 + 8];
            float rm1 = fmaxf(fmaxf(m4b.x, m4b.y), fmaxf(m4b.z, m4b.w));
#pragma unroll
            for (int nt = 0; nt < 8; ++nt) {
                int c0 = wn * 64 + nt * 8 + 2 * tq;
                __half2 hp0 = __floats2half2_rn(__expf(sacc[mt][nt][0] - rm0),
                                                __expf(sacc[mt][nt][1] - rm0));
                __half2 hp1 = __floats2half2_rn(__expf(sacc[mt][nt][2] - rm1),
                                                __expf(sacc[mt][nt][3] - rm1));
                *(__half2*)&sm->P16[r0][c0]     = hp0;
                *(__half2*)&sm->P16[r0 + 8][c0] = hp1;
                float2 p0f = __half22float2(hp0);
                float2 p1f = __half22float2(hp1);
                psum[mt][0] += p0f.x + p0f.y;
                psum[mt][1] += p1f.x + p1f.y;
            }
        }
#pragma unroll
        for (int mt = 0; mt < 2; ++mt)
#pragma unroll
            for (int rh = 0; rh < 2; ++rh) {
                float v = psum[mt][rh];
                v += __shfl_xor_sync(0xffffffffu, v, 1);
                v += __shfl_xor_sync(0xffffffffu, v, 2);
                psum[mt][rh] = v;
            }
        if (tq == 0) {
#pragma unroll
            for (int mt = 0; mt < 2; ++mt) {
                int r0 = wm * 32 + mt * 16 + g;
                sm->rsum[r0][wn]     = psum[mt][0];
                sm->rsum[r0 + 8][wn] = psum[mt][1];
            }
        }
        __syncthreads();

        // ---- O = P V : fp16 m16n8k16, 16 k-steps, warp tile 32x8 ----
        int nb = wn * 8;
        float oacc[2][4] = {{0,0,0,0},{0,0,0,0}};
#pragma unroll
        for (int ks16 = 0; ks16 < 16; ++ks16) {
            int kk = ks16 * 16;
            uint32_t b0 = *(const uint32_t*)&sm->Vt[nb + g][kk + 2 * tq];
            uint32_t b1 = *(const uint32_t*)&sm->Vt[nb + g][kk + 2 * tq + 8];
#pragma unroll
            for (int mt = 0; mt < 2; ++mt) {
                int r0 = wm * 32 + mt * 16 + g;
                uint32_t a0 = *(const uint32_t*)&sm->P16[r0][kk + 2 * tq];
                uint32_t a1 = *(const uint32_t*)&sm->P16[r0 + 8][kk + 2 * tq];
                uint32_t a2 = *(const uint32_t*)&sm->P16[r0][kk + 2 * tq + 8];
                uint32_t a3 = *(const uint32_t*)&sm->P16[r0 + 8][kk + 2 * tq + 8];
                mma_f16(oacc[mt][0], oacc[mt][1], oacc[mt][2], oacc[mt][3],
                        a0, a1, a2, a3, b0, b1);
            }
        }

        // ---- epilogue: normalize, apply sigmoid gate, store gated fp16 ----
#pragma unroll
        for (int mt = 0; mt < 2; ++mt) {
            int r0 = wm * 32 + mt * 16 + g;
            float4 s0 = *(float4*)sm->rsum[r0];
            float inv0 = 1.0f / (s0.x + s0.y + s0.z + s0.w);
            float4 s1 = *(float4*)sm->rsum[r0 + 8];
            float inv1 = 1.0f / (s1.x + s1.y + s1.z + s1.w);
            int col = nb + 2 * tq;
            float bga = bg[h * 32 + col], bgb = bg[h * 32 + col + 1];
            int gr0 = q0 + r0, gr1 = q0 + r0 + 8;
            float d00 = 1.0f + __expf(-(sm->Gs[gr0][col]     + bga));
            float d01 = 1.0f + __expf(-(sm->Gs[gr0][col + 1] + bgb));
            float d10 = 1.0f + __expf(-(sm->Gs[gr1][col]     + bga));
            float d11 = 1.0f + __expf(-(sm->Gs[gr1][col + 1] + bgb));
            size_t b0a = ((size_t)(i * N + gr0)) * C + h * D + col;
            *(__half2*)&g_o[b0a] = __floats2half2_rn((oacc[mt][0] * inv0) / d00,
                                                     (oacc[mt][1] * inv0) / d01);
            size_t b1a = ((size_t)(i * N + gr1)) * C + h * D + col;
            *(__half2*)&g_o[b1a] = __floats2half2_rn((oacc[mt][2] * inv1) / d10,
                                                     (oacc[mt][3] * inv1) / d11);
        }
    }
}

// ---------------------------------------------------------------------------
// Kernel 3: output projection, fp16 MMA. grid=NP/128, 2 blocks/SM.
// B (wo, fp16) resident; A (gated o, fp16) streamed with register prefetch.
// ---------------------------------------------------------------------------
struct OutSmem {
    __half Bs[128][136];    // resident wo (fp16)   34816 B
    __half As[2][128][40];  // A chunks (fp16)      20480 B
};                          // 55296 B

__global__ void __launch_bounds__(256, 2)
k_out(const float* __restrict__ wo, const float* __restrict__ bo,
      float* __restrict__ out) {
    extern __shared__ char smraw[];
    OutSmem* sm = (OutSmem*)smraw;
    int tid = threadIdx.x;
    int m0 = blockIdx.x * 128;
    int w = tid >> 5, lane = tid & 31;
    int wm = w >> 1, wn = w & 1;
    int g = lane >> 2, tq = lane & 3;

    // stage full B (wo -> fp16)
#pragma unroll
    for (int t = 0; t < 16; ++t) {
        int idx = tid + t * 256;
        int row = idx >> 5, j4 = idx & 31;
        float4 b = *(const float4*)&wo[(size_t)row * C + j4 * 4];
        *(uint2*)&sm->Bs[row][j4 * 4] = make_uint2(f2h2(b.x, b.y), f2h2(b.z, b.w));
    }
    // stage A chunk 0 (bit copy from fp16 g_o)
#pragma unroll
    for (int t = 0; t < 2; ++t) {
        int idx = tid + t * 256;            // 0..511
        int row = idx >> 2, j8 = idx & 3;
        uint4 v = *(const uint4*)&g_o[(size_t)(m0 + row) * C + j8 * 8];
        *(uint4*)&sm->As[0][row][j8 * 8] = v;
    }
    __syncthreads();

    float acc[2][8][4];
#pragma unroll
    for (int mt = 0; mt < 2; ++mt)
#pragma unroll
        for (int nt = 0; nt < 8; ++nt)
#pragma unroll
            for (int r = 0; r < 4; ++r) acc[mt][nt][r] = 0.0f;

    for (int kc = 0; kc < 4; ++kc) {
        uint4 po[2];
        if (kc < 3) {
#pragma unroll
            for (int t = 0; t < 2; ++t) {
                int idx = tid + t * 256;
                int row = idx >> 2, j8 = idx & 3;
                po[t] = *(const uint4*)&g_o[(size_t)(m0 + row) * C + (kc + 1) * 32 + j8 * 8];
            }
        }
        // MMA over this 32-wide chunk: 2 k-steps of m16n8k16
        int cbase = kc * 32;
#pragma unroll
        for (int ks = 0; ks < 32; ks += 16) {
            uint32_t af[2][4];
#pragma unroll
            for (int mt = 0; mt < 2; ++mt) {
                int r = wm * 32 + mt * 16;
                af[mt][0] = *(const uint32_t*)&sm->As[kc & 1][r + g][ks + 2 * tq];
                af[mt][1] = *(const uint32_t*)&sm->As[kc & 1][r + g + 8][ks + 2 * tq];
                af[mt][2] = *(const uint32_t*)&sm->As[kc & 1][r + g][ks + 2 * tq + 8];
                af[mt][3] = *(const uint32_t*)&sm->As[kc & 1][r + g + 8][ks + 2 * tq + 8];
            }
#pragma unroll
            for (int nt = 0; nt < 8; ++nt) {
                int cb = wn * 64 + nt * 8;
                uint32_t b0 = *(const uint32_t*)&sm->Bs[cb + g][cbase + ks + 2 * tq];
                uint32_t b1 = *(const uint32_t*)&sm->Bs[cb + g][cbase + ks + 2 * tq + 8];
#pragma unroll
                for (int mt = 0; mt < 2; ++mt)
                    mma_f16(acc[mt][nt][0], acc[mt][nt][1], acc[mt][nt][2], acc[mt][nt][3],
                            af[mt][0], af[mt][1], af[mt][2], af[mt][3], b0, b1);
            }
        }
        if (kc < 3) {
            __syncthreads();
#pragma unroll
            for (int t = 0; t < 2; ++t) {
                int idx = tid + t * 256;
                int row = idx >> 2, j8 = idx & 3;
                *(uint4*)&sm->As[(kc + 1) & 1][row][j8 * 8] = po[t];
            }
            __syncthreads();
        }
    }

#pragma unroll
    for (int mt = 0; mt < 2; ++mt) {
        int r0 = m0 + wm * 32 + mt * 16 + g;
#pragma unroll
        for (int nt = 0; nt < 8; ++nt) {
            int cb = wn * 64 + nt * 8 + 2 * tq;
            float2 bov = *(const float2*)&bo[cb];
            *(float2*)&out[(size_t)r0 * C + cb] =
                make_float2(acc[mt][nt][0] + bov.x, acc[mt][nt][1] + bov.y);
            *(float2*)&out[(size_t)(r0 + 8) * C + cb] =
                make_float2(acc[mt][nt][2] + bov.x, acc[mt][nt][3] + bov.y);
        }
    }
}

// ---------------------------------------------------------------------------
extern "C" void kernel_launch(void* const* d_in, const int* in_sizes, int n_in,
                              void* d_out, int out_size) {
    const float* x     = (const float*)d_in[0];
    const float* mask  = (const float*)d_in[1];
    const float* ln_w  = (const float*)d_in[2];
    const float* ln_b  = (const float*)d_in[3];
    const float* w_tri = (const float*)d_in[4];
    const float* wq    = (const float*)d_in[5];
    const float* wk    = (const float*)d_in[6];
    const float* wv    = (const float*)d_in[7];
    const float* wg    = (const float*)d_in[8];
    const float* bg    = (const float*)d_in[9];
    const float* wo    = (const float*)d_in[10];
    const float* bo    = (const float*)d_in[11];
    float* out = (float*)d_out;

    (void)in_sizes; (void)n_in; (void)out_size;

    cudaFuncSetAttribute(k_out, cudaFuncAttributeMaxDynamicSharedMemorySize,
                         (int)sizeof(OutSmem));
    cudaFuncSetAttribute(k_attn, cudaFuncAttributeMaxDynamicSharedMemorySize,
                         (int)sizeof(AttnSmem));

    k_ln_tri<<<NP / 8, 256>>>(x, ln_w, ln_b, w_tri);
    k_attn<<<dim3(N, H), 256, sizeof(AttnSmem)>>>(mask, wq, wk, wv, wg, bg);
    k_out<<<NP / 128, 256, sizeof(OutSmem)>>>(wo, bo, out);
}

// round 17
// speedup vs baseline: 1.5426x; 1.0277x over previous
#include <cuda_runtime.h>
#include <cuda_fp16.h>
#include <math.h>
#include <stdint.h>

#define N 256
#define C 128
#define H 4
#define D 32
#define NP (N*N)            // 65536 positions
#define EPSV 1e-5f
#define INFV 1000000000.0f
#define QT 64               // attention query tile

// Scratch (static device arrays; no allocation in kernel_launch)
__device__ __half g_xn[NP*C];       // layernormed x, fp16   16 MB
__device__ float  g_tri[H*N*N];     // tri bias [h][q][k]     1 MB
__device__ __half g_o[NP*C];        // gated attn output     16 MB

__device__ __forceinline__ uint32_t f2h2(float x, float y) {
    __half2 h = __floats2half2_rn(x, y);
    return *(uint32_t*)&h;
}

// fp16 MMA m16n8k16, fp32 accumulate
__device__ __forceinline__ void mma_f16(float& d0, float& d1, float& d2, float& d3,
                                        uint32_t a0, uint32_t a1, uint32_t a2, uint32_t a3,
                                        uint32_t b0, uint32_t b1) {
    asm volatile(
        "mma.sync.aligned.m16n8k16.row.col.f32.f16.f16.f32 "
        "{%0,%1,%2,%3}, {%4,%5,%6,%7}, {%8,%9}, {%0,%1,%2,%3};\n"
        : "+f"(d0), "+f"(d1), "+f"(d2), "+f"(d3)
        : "r"(a0), "r"(a1), "r"(a2), "r"(a3), "r"(b0), "r"(b1));
}

// 16-byte async copy global -> shared
__device__ __forceinline__ void cpa16(void* smem_dst, const void* gmem_src) {
    uint32_t s = (uint32_t)__cvta_generic_to_shared(smem_dst);
    asm volatile("cp.async.cg.shared.global [%0], [%1], 16;\n" :: "r"(s), "l"(gmem_src));
}

// ---------------------------------------------------------------------------
// Kernel 1: LayerNorm over C + triangle-bias projection ([h][q][k] layout).
// g_xn stored fp16; tri computed from unrounded fp32 values.
// ---------------------------------------------------------------------------
__global__ void k_ln_tri(const float* __restrict__ x,
                         const float* __restrict__ ln_w,
                         const float* __restrict__ ln_b,
                         const float* __restrict__ w_tri) {
    __shared__ float swt[H*C];
    int tid = threadIdx.x;
    swt[tid]       = w_tri[tid];
    swt[tid + 256] = w_tri[tid + 256];
    __syncthreads();

    int warp = tid >> 5, lane = tid & 31;
    int pos = (blockIdx.x << 3) + warp;

    const float4 a = ((const float4*)(x + (size_t)pos * C))[lane];
    float s  = a.x + a.y + a.z + a.w;
    float s2 = a.x*a.x + a.y*a.y + a.z*a.z + a.w*a.w;
#pragma unroll
    for (int o = 16; o > 0; o >>= 1) {
        s  += __shfl_xor_sync(0xffffffffu, s,  o);
        s2 += __shfl_xor_sync(0xffffffffu, s2, o);
    }
    float mu   = s * (1.0f / C);
    float var  = s2 * (1.0f / C) - mu * mu;
    float rstd = rsqrtf(var + EPSV);

    float4 w = ((const float4*)ln_w)[lane];
    float4 b = ((const float4*)ln_b)[lane];
    float4 xn;
    xn.x = (a.x - mu) * rstd * w.x + b.x;
    xn.y = (a.y - mu) * rstd * w.y + b.y;
    xn.z = (a.z - mu) * rstd * w.z + b.z;
    xn.w = (a.w - mu) * rstd * w.w + b.w;
    ((uint2*)(g_xn + (size_t)pos * C))[lane] =
        make_uint2(f2h2(xn.x, xn.y), f2h2(xn.z, xn.w));

    // tri from fp32 xn; packed 4-head reduction (6 shuffles)
    float t0, t1, t2, t3;
    {
        const float4 w0 = ((const float4*)(swt + 0 * C))[lane];
        const float4 w1 = ((const float4*)(swt + 1 * C))[lane];
        const float4 w2 = ((const float4*)(swt + 2 * C))[lane];
        const float4 w3 = ((const float4*)(swt + 3 * C))[lane];
        t0 = xn.x*w0.x + xn.y*w0.y + xn.z*w0.z + xn.w*w0.w;
        t1 = xn.x*w1.x + xn.y*w1.y + xn.z*w1.z + xn.w*w1.w;
        t2 = xn.x*w2.x + xn.y*w2.y + xn.z*w2.z + xn.w*w2.w;
        t3 = xn.x*w3.x + xn.y*w3.y + xn.z*w3.z + xn.w*w3.w;
    }
    bool o1 = lane & 1;
    float a01 = o1 ? t1 : t0;
    float b01 = o1 ? t0 : t1;
    a01 += __shfl_xor_sync(0xffffffffu, b01, 1);
    float a23 = o1 ? t3 : t2;
    float b23 = o1 ? t2 : t3;
    a23 += __shfl_xor_sync(0xffffffffu, b23, 1);
    bool o2 = lane & 2;
    float cc = o2 ? a23 : a01;
    float dd = o2 ? a01 : a23;
    cc += __shfl_xor_sync(0xffffffffu, dd, 2);
    cc += __shfl_xor_sync(0xffffffffu, cc, 4);
    cc += __shfl_xor_sync(0xffffffffu, cc, 8);
    cc += __shfl_xor_sync(0xffffffffu, cc, 16);

    if (lane < 4) {
        int q = pos >> 8, k = pos & 255;
        g_tri[((size_t)(lane * N + q)) * N + k] = cc;   // head = lane
    }
}

// ---------------------------------------------------------------------------
// Kernel 2: fused K/V/Q/gate projection + fp16-MMA attention + gated epilogue.
// Block = (i, h), 256 threads (8 warps).
// Phase 1: double-buffered Xs, ONE barrier per chunk.
// Phase 2: tri tile streamed via cp.async, overlapped with exp+PV.
// ---------------------------------------------------------------------------
struct AttnSmem {
    union {
        struct {
            __half W4[128][136];     // stacked [k|v|q|g] head weights  34816 B
            __half Xs[2][32][136];   // xn chunks, double-buffered      17408 B
        } p;                         // 52224 B
        float T[QT][260];            // tri bias (fp32)                 66560 B
    } u;                             // 66560 B
    __half Ks[256][40];           // K (fp16), pitch 40h = 20 words  20480 B
    __half Qs[256][40];           // Q pre-scaled (fp16)             20480 B
    __half Vt[32][264];           // V transposed [d][key] (fp16)    16896 B
    __half P16[QT][264];          // softmax P (fp16)                33792 B
    float Gs[256][33];            // gate logits, raw fp32           33792 B
    float mb[256];                //  1024 B
    float rmax[QT][4];            //  1024 B
    float rsum[QT][4];            //  1024 B
};                                // 195072 B

__global__ void __launch_bounds__(256)
k_attn(const float* __restrict__ mask,
       const float* __restrict__ wq, const float* __restrict__ wk,
       const float* __restrict__ wv, const float* __restrict__ wg,
       const float* __restrict__ bg) {
    extern __shared__ char smraw[];
    AttnSmem* sm = (AttnSmem*)smraw;

    int i = blockIdx.x, h = blockIdx.y;
    int tid = threadIdx.x, w = tid >> 5, lane = tid & 31;
    int g = lane >> 2, tq = lane & 3;
    const float sc = 0.17677669529663688f;  // 1/sqrt(32)

    // ===================== Phase 1: project K/V/Q/gate (fp16 MMA) ==========
    // W4 rows: 0-31 Wk_h, 32-63 Wv_h, 64-95 Wq_h, 96-127 Wg slice [h*32, +32)
    {
        int pwm = w >> 2, pwn = w & 3;    // 2 warps M(32), 4 warps N(128)
#pragma unroll
        for (int t = 0; t < 16; ++t) {
            int idx = tid + t * 256;      // 0..4095
            int row = idx >> 5, j4 = idx & 31;
            const float* src = (row < 32) ? wk : (row < 64) ? wv : (row < 96) ? wq : wg;
            float4 b = *(const float4*)&src[(size_t)(h * 32 + (row & 31)) * C + j4 * 4];
            *(uint2*)&sm->u.p.W4[row][j4 * 4] = make_uint2(f2h2(b.x, b.y), f2h2(b.z, b.w));
        }
        sm->mb[tid] = INFV * (mask[i * N + tid] - 1.0f);

        const __half* Xg = g_xn + (size_t)(i * N) * C;
        // stage xn chunk 0 into Xs[0] — pure bit copy
        uint4 xpre[2];
#pragma unroll
        for (int t = 0; t < 2; ++t) {
            int idx = tid + t * 256;      // 0..511
            int row = idx >> 4, j8 = idx & 15;
            xpre[t] = *(const uint4*)&Xg[(size_t)row * C + j8 * 8];
        }
#pragma unroll
        for (int t = 0; t < 2; ++t) {
            int idx = tid + t * 256;
            int row = idx >> 4, j8 = idx & 15;
            *(uint4*)&sm->u.p.Xs[0][row][j8 * 8] = xpre[t];
        }
        __syncthreads();

        for (int c = 0; c < 8; ++c) {
            if (c < 7) {
#pragma unroll
                for (int t = 0; t < 2; ++t) {
                    int idx = tid + t * 256;
                    int row = idx >> 4, j8 = idx & 15;
                    xpre[t] = *(const uint4*)&Xg[(size_t)((c + 1) * 32 + row) * C + j8 * 8];
                }
            }
            // GEMM: M=32, N=128, K=128. fp16 m16n8k16, 8 k-steps.
            const __half (*Xc)[136] = sm->u.p.Xs[c & 1];
            float pacc[4][4] = {};
#pragma unroll
            for (int ks = 0; ks < 128; ks += 16) {
                int r = pwm * 16;
                uint32_t a0 = *(const uint32_t*)&Xc[r + g][ks + 2 * tq];
                uint32_t a1 = *(const uint32_t*)&Xc[r + g + 8][ks + 2 * tq];
                uint32_t a2 = *(const uint32_t*)&Xc[r + g][ks + 2 * tq + 8];
                uint32_t a3 = *(const uint32_t*)&Xc[r + g + 8][ks + 2 * tq + 8];
#pragma unroll
                for (int nt = 0; nt < 4; ++nt) {
                    int cb = pwn * 32 + nt * 8;
                    uint32_t b0 = *(const uint32_t*)&sm->u.p.W4[cb + g][ks + 2 * tq];
                    uint32_t b1 = *(const uint32_t*)&sm->u.p.W4[cb + g][ks + 2 * tq + 8];
                    mma_f16(pacc[nt][0], pacc[nt][1], pacc[nt][2], pacc[nt][3],
                            a0, a1, a2, a3, b0, b1);
                }
            }
            // scatter: pwn -> 0=K, 1=V(transposed), 2=Q(scaled), 3=gate(fp32)
            {
                int row0 = c * 32 + pwm * 16 + g;
#pragma unroll
                for (int nt = 0; nt < 4; ++nt) {
                    int off = nt * 8 + 2 * tq;
                    float m0 = pacc[nt][0], m1 = pacc[nt][1];
                    float m2 = pacc[nt][2], m3 = pacc[nt][3];
                    if (pwn == 3) {
                        sm->Gs[row0][off]         = m0;
                        sm->Gs[row0][off + 1]     = m1;
                        sm->Gs[row0 + 8][off]     = m2;
                        sm->Gs[row0 + 8][off + 1] = m3;
                    } else if (pwn == 1) {
                        sm->Vt[off][row0]         = __float2half_rn(m0);
                        sm->Vt[off + 1][row0]     = __float2half_rn(m1);
                        sm->Vt[off][row0 + 8]     = __float2half_rn(m2);
                        sm->Vt[off + 1][row0 + 8] = __float2half_rn(m3);
                    } else {
                        if (pwn == 2) { m0 *= sc; m1 *= sc; m2 *= sc; m3 *= sc; }
                        __half* dst = (pwn == 0) ? &sm->Ks[0][0] : &sm->Qs[0][0];
                        *(uint32_t*)&dst[row0 * 40 + off]       = f2h2(m0, m1);
                        *(uint32_t*)&dst[(row0 + 8) * 40 + off] = f2h2(m2, m3);
                    }
                }
            }
            if (c < 7) {
                // store into the OTHER buffer; its last readers finished at the
                // end of iteration c-1 (behind that iteration's barrier)
#pragma unroll
                for (int t = 0; t < 2; ++t) {
                    int idx = tid + t * 256;
                    int row = idx >> 4, j8 = idx & 15;
                    *(uint4*)&sm->u.p.Xs[(c + 1) & 1][row][j8 * 8] = xpre[t];
                }
                __syncthreads();
            }
        }
    }

    // ===================== Phase 2: attention =====================
    int wm = w >> 2, wn = w & 3;          // 2 warps along M(64), 4 along N(256)

    __syncthreads();   // phase-1 complete: W4/Xs dead, K/V/Q/Gs visible

    // stream tri(qt=0) into T via cp.async
#pragma unroll
    for (int t = 0; t < 16; ++t) {
        int idx = tid + t * 256;           // 0..4095
        int row = idx >> 6, k4 = idx & 63;
        cpa16(&sm->u.T[row][k4 * 4], &g_tri[((size_t)(h * N + row)) * N + k4 * 4]);
    }
    asm volatile("cp.async.commit_group;\n");
    asm volatile("cp.async.wait_group 0;\n");
    __syncthreads();

    for (int qt = 0; qt < 4; ++qt) {
        int q0 = qt * QT;

        // ---- S = Q K^T : fp16 m16n8k16, 2 k-steps, 2mt x 8nt ----
        float sacc[2][8][4];
#pragma unroll
        for (int mt = 0; mt < 2; ++mt)
#pragma unroll
            for (int nt = 0; nt < 8; ++nt)
#pragma unroll
                for (int r = 0; r < 4; ++r) sacc[mt][nt][r] = 0.0f;

#pragma unroll
        for (int ks = 0; ks < 32; ks += 16) {
            uint32_t af[2][4];
#pragma unroll
            for (int mt = 0; mt < 2; ++mt) {
                int r = q0 + wm * 32 + mt * 16;
                af[mt][0] = *(const uint32_t*)&sm->Qs[r + g][ks + 2 * tq];
                af[mt][1] = *(const uint32_t*)&sm->Qs[r + g + 8][ks + 2 * tq];
                af[mt][2] = *(const uint32_t*)&sm->Qs[r + g][ks + 2 * tq + 8];
                af[mt][3] = *(const uint32_t*)&sm->Qs[r + g + 8][ks + 2 * tq + 8];
            }
#pragma unroll
            for (int nt = 0; nt < 8; ++nt) {
                int cb = wn * 64 + nt * 8;
                uint32_t b0 = *(const uint32_t*)&sm->Ks[cb + g][ks + 2 * tq];
                uint32_t b1 = *(const uint32_t*)&sm->Ks[cb + g][ks + 2 * tq + 8];
#pragma unroll
                for (int mt = 0; mt < 2; ++mt)
                    mma_f16(sacc[mt][nt][0], sacc[mt][nt][1], sacc[mt][nt][2], sacc[mt][nt][3],
                            af[mt][0], af[mt][1], af[mt][2], af[mt][3], b0, b1);
            }
        }

        // ---- add tri + mask bias; partial row max ----
        float pmax[2][2];
        pmax[0][0] = pmax[0][1] = pmax[1][0] = pmax[1][1] = -3.4e38f;
#pragma unroll
        for (int mt = 0; mt < 2; ++mt) {
            int r0 = wm * 32 + mt * 16 + g;
#pragma unroll
            for (int nt = 0; nt < 8; ++nt) {
                int c0 = wn * 64 + nt * 8 + 2 * tq;
                float m0v = sm->mb[c0], m1v = sm->mb[c0 + 1];
                sacc[mt][nt][0] += sm->u.T[r0][c0]     + m0v;
                sacc[mt][nt][1] += sm->u.T[r0][c0 + 1] + m1v;
                sacc[mt][nt][2] += sm->u.T[r0 + 8][c0]     + m0v;
                sacc[mt][nt][3] += sm->u.T[r0 + 8][c0 + 1] + m1v;
                pmax[mt][0] = fmaxf(pmax[mt][0], fmaxf(sacc[mt][nt][0], sacc[mt][nt][1]));
                pmax[mt][1] = fmaxf(pmax[mt][1], fmaxf(sacc[mt][nt][2], sacc[mt][nt][3]));
            }
        }
#pragma unroll
        for (int mt = 0; mt < 2; ++mt)
#pragma unroll
            for (int rh = 0; rh < 2; ++rh) {
                float v = pmax[mt][rh];
                v = fmaxf(v, __shfl_xor_sync(0xffffffffu, v, 1));
                v = fmaxf(v, __shfl_xor_sync(0xffffffffu, v, 2));
                pmax[mt][rh] = v;
            }
        if (tq == 0) {
#pragma unroll
            for (int mt = 0; mt < 2; ++mt) {
                int r0 = wm * 32 + mt * 16 + g;
                sm->rmax[r0][wn]     = pmax[mt][0];
                sm->rmax[r0 + 8][wn] = pmax[mt][1];
            }
        }
        __syncthreads();   // all bias-adds done -> T is dead

        // ---- stream tri(qt+1) into T, overlapped with exp + PV ----
        if (qt < 3) {
            int q1 = q0 + QT;
#pragma unroll
            for (int t = 0; t < 16; ++t) {
                int idx = tid + t * 256;
                int row = idx >> 6, k4 = idx & 63;
                cpa16(&sm->u.T[row][k4 * 4],
                      &g_tri[((size_t)(h * N + q1 + row)) * N + k4 * 4]);
            }
            asm volatile("cp.async.commit_group;\n");
        }

        // ---- exp + write P (fp16) + partial row sums ----
        float psum[2][2] = {{0.0f, 0.0f}, {0.0f, 0.0f}};
#pragma unroll
        for (int mt = 0; mt < 2; ++mt) {
            int r0 = wm * 32 + mt * 16 + g;
            float4 m4a = *(float4*)sm->rmax[r0];
            float rm0 = fmaxf(fmaxf(m4a.x, m4a.y), fmaxf(m4a.z, m4a.w));
            float4 m4b = *(float4*)sm->rmax[r0 + 8];
            float rm1 = fmaxf(fmaxf(m4b.x, m4b.y), fmaxf(m4b.z, m4b.w));
#pragma unroll
            for (int nt = 0; nt < 8; ++nt) {
                int c0 = wn * 64 + nt * 8 + 2 * tq;
                __half2 hp0 = __floats2half2_rn(__expf(sacc[mt][nt][0] - rm0),
                                                __expf(sacc[mt][nt][1] - rm0));
                __half2 hp1 = __floats2half2_rn(__expf(sacc[mt][nt][2] - rm1),
                                                __expf(sacc[mt][nt][3] - rm1));
                *(__half2*)&sm->P16[r0][c0]     = hp0;
                *(__half2*)&sm->P16[r0 + 8][c0] = hp1;
                float2 p0f = __half22float2(hp0);
                float2 p1f = __half22float2(hp1);
                psum[mt][0] += p0f.x + p0f.y;
                psum[mt][1] += p1f.x + p1f.y;
            }
        }
#pragma unroll
        for (int mt = 0; mt < 2; ++mt)
#pragma unroll
            for (int rh = 0; rh < 2; ++rh) {
                float v = psum[mt][rh];
                v += __shfl_xor_sync(0xffffffffu, v, 1);
                v += __shfl_xor_sync(0xffffffffu, v, 2);
                psum[mt][rh] = v;
            }
        if (tq == 0) {
#pragma unroll
            for (int mt = 0; mt < 2; ++mt) {
                int r0 = wm * 32 + mt * 16 + g;
                sm->rsum[r0][wn]     = psum[mt][0];
                sm->rsum[r0 + 8][wn] = psum[mt][1];
            }
        }
        __syncthreads();

        // ---- O = P V : fp16 m16n8k16, 16 k-steps, warp tile 32x8 ----
        int nb = wn * 8;
        float oacc[2][4] = {{0,0,0,0},{0,0,0,0}};
#pragma unroll
        for (int ks16 = 0; ks16 < 16; ++ks16) {
            int kk = ks16 * 16;
            uint32_t b0 = *(const uint32_t*)&sm->Vt[nb + g][kk + 2 * tq];
            uint32_t b1 = *(const uint32_t*)&sm->Vt[nb + g][kk + 2 * tq + 8];
#pragma unroll
            for (int mt = 0; mt < 2; ++mt) {
                int r0 = wm * 32 + mt * 16 + g;
                uint32_t a0 = *(const uint32_t*)&sm->P16[r0][kk + 2 * tq];
                uint32_t a1 = *(const uint32_t*)&sm->P16[r0 + 8][kk + 2 * tq];
                uint32_t a2 = *(const uint32_t*)&sm->P16[r0][kk + 2 * tq + 8];
                uint32_t a3 = *(const uint32_t*)&sm->P16[r0 + 8][kk + 2 * tq + 8];
                mma_f16(oacc[mt][0], oacc[mt][1], oacc[mt][2], oacc[mt][3],
                        a0, a1, a2, a3, b0, b1);
            }
        }

        // ---- epilogue: normalize, apply sigmoid gate, store gated fp16 ----
#pragma unroll
        for (int mt = 0; mt < 2; ++mt) {
            int r0 = wm * 32 + mt * 16 + g;
            float4 s0 = *(float4*)sm->rsum[r0];
            float inv0 = 1.0f / (s0.x + s0.y + s0.z + s0.w);
            float4 s1 = *(float4*)sm->rsum[r0 + 8];
            float inv1 = 1.0f / (s1.x + s1.y + s1.z + s1.w);
            int col = nb + 2 * tq;
            float bga = bg[h * 32 + col], bgb = bg[h * 32 + col + 1];
            int gr0 = q0 + r0, gr1 = q0 + r0 + 8;
            float d00 = 1.0f + __expf(-(sm->Gs[gr0][col]     + bga));
            float d01 = 1.0f + __expf(-(sm->Gs[gr0][col + 1] + bgb));
            float d10 = 1.0f + __expf(-(sm->Gs[gr1][col]     + bga));
            float d11 = 1.0f + __expf(-(sm->Gs[gr1][col + 1] + bgb));
            size_t b0a = ((size_t)(i * N + gr0)) * C + h * D + col;
            *(__half2*)&g_o[b0a] = __floats2half2_rn((oacc[mt][0] * inv0) / d00,
                                                     (oacc[mt][1] * inv0) / d01);
            size_t b1a = ((size_t)(i * N + gr1)) * C + h * D + col;
            *(__half2*)&g_o[b1a] = __floats2half2_rn((oacc[mt][2] * inv1) / d10,
                                                     (oacc[mt][3] * inv1) / d11);
        }

        if (qt < 3) {
            asm volatile("cp.async.wait_group 0;\n");
            __syncthreads();   // publish tri(qt+1) to all threads
        }
    }
}

// ---------------------------------------------------------------------------
// Kernel 3: output projection, fp16 MMA. grid=NP/128, 2 blocks/SM.
// B (wo, fp16) resident; A (gated o, fp16) streamed with register prefetch.
// ---------------------------------------------------------------------------
struct OutSmem {
    __half Bs[128][136];    // resident wo (fp16)   34816 B
    __half As[2][128][40];  // A chunks (fp16)      20480 B
};                          // 55296 B

__global__ void __launch_bounds__(256, 2)
k_out(const float* __restrict__ wo, const float* __restrict__ bo,
      float* __restrict__ out) {
    extern __shared__ char smraw[];
    OutSmem* sm = (OutSmem*)smraw;
    int tid = threadIdx.x;
    int m0 = blockIdx.x * 128;
    int w = tid >> 5, lane = tid & 31;
    int wm = w >> 1, wn = w & 1;
    int g = lane >> 2, tq = lane & 3;

    // stage full B (wo -> fp16)
#pragma unroll
    for (int t = 0; t < 16; ++t) {
        int idx = tid + t * 256;
        int row = idx >> 5, j4 = idx & 31;
        float4 b = *(const float4*)&wo[(size_t)row * C + j4 * 4];
        *(uint2*)&sm->Bs[row][j4 * 4] = make_uint2(f2h2(b.x, b.y), f2h2(b.z, b.w));
    }
    // stage A chunk 0 (bit copy from fp16 g_o)
#pragma unroll
    for (int t = 0; t < 2; ++t) {
        int idx = tid + t * 256;            // 0..511
        int row = idx >> 2, j8 = idx & 3;
        uint4 v = *(const uint4*)&g_o[(size_t)(m0 + row) * C + j8 * 8];
        *(uint4*)&sm->As[0][row][j8 * 8] = v;
    }
    __syncthreads();

    float acc[2][8][4];
#pragma unroll
    for (int mt = 0; mt < 2; ++mt)
#pragma unroll
        for (int nt = 0; nt < 8; ++nt)
#pragma unroll
            for (int r = 0; r < 4; ++r) acc[mt][nt][r] = 0.0f;

    for (int kc = 0; kc < 4; ++kc) {
        uint4 po[2];
        if (kc < 3) {
#pragma unroll
            for (int t = 0; t < 2; ++t) {
                int idx = tid + t * 256;
                int row = idx >> 2, j8 = idx & 3;
                po[t] = *(const uint4*)&g_o[(size_t)(m0 + row) * C + (kc + 1) * 32 + j8 * 8];
            }
        }
        // MMA over this 32-wide chunk: 2 k-steps of m16n8k16
        int cbase = kc * 32;
#pragma unroll
        for (int ks = 0; ks < 32; ks += 16) {
            uint32_t af[2][4];
#pragma unroll
            for (int mt = 0; mt < 2; ++mt) {
                int r = wm * 32 + mt * 16;
                af[mt][0] = *(const uint32_t*)&sm->As[kc & 1][r + g][ks + 2 * tq];
                af[mt][1] = *(const uint32_t*)&sm->As[kc & 1][r + g + 8][ks + 2 * tq];
                af[mt][2] = *(const uint32_t*)&sm->As[kc & 1][r + g][ks + 2 * tq + 8];
                af[mt][3] = *(const uint32_t*)&sm->As[kc & 1][r + g + 8][ks + 2 * tq + 8];
            }
#pragma unroll
            for (int nt = 0; nt < 8; ++nt) {
                int cb = wn * 64 + nt * 8;
                uint32_t b0 = *(const uint32_t*)&sm->Bs[cb + g][cbase + ks + 2 * tq];
                uint32_t b1 = *(const uint32_t*)&sm->Bs[cb + g][cbase + ks + 2 * tq + 8];
#pragma unroll
                for (int mt = 0; mt < 2; ++mt)
                    mma_f16(acc[mt][nt][0], acc[mt][nt][1], acc[mt][nt][2], acc[mt][nt][3],
                            af[mt][0], af[mt][1], af[mt][2], af[mt][3], b0, b1);
            }
        }
        if (kc < 3) {
            __syncthreads();
#pragma unroll
            for (int t = 0; t < 2; ++t) {
                int idx = tid + t * 256;
                int row = idx >> 2, j8 = idx & 3;
                *(uint4*)&sm->As[(kc + 1) & 1][row][j8 * 8] = po[t];
            }
            __syncthreads();
        }
    }

#pragma unroll
    for (int mt = 0; mt < 2; ++mt) {
        int r0 = m0 + wm * 32 + mt * 16 + g;
#pragma unroll
        for (int nt = 0; nt < 8; ++nt) {
            int cb = wn * 64 + nt * 8 + 2 * tq;
            float2 bov = *(const float2*)&bo[cb];
            *(float2*)&out[(size_t)r0 * C + cb] =
                make_float2(acc[mt][nt][0] + bov.x, acc[mt][nt][1] + bov.y);
            *(float2*)&out[(size_t)(r0 + 8) * C + cb] =
                make_float2(acc[mt][nt][2] + bov.x, acc[mt][nt][3] + bov.y);
        }
    }
}

// ---------------------------------------------------------------------------
extern "C" void kernel_launch(void* const* d_in, const int* in_sizes, int n_in,
                              void* d_out, int out_size) {
    const float* x     = (const float*)d_in[0];
    const float* mask  = (const float*)d_in[1];
    const float* ln_w  = (const float*)d_in[2];
    const float* ln_b  = (const float*)d_in[3];
    const float* w_tri = (const float*)d_in[4];
    const float* wq    = (const float*)d_in[5];
    const float* wk    = (const float*)d_in[6];
    const float* wv    = (const float*)d_in[7];
    const float* wg    = (const float*)d_in[8];
    const float* bg    = (const float*)d_in[9];
    const float* wo    = (const float*)d_in[10];
    const float* bo    = (const float*)d_in[11];
    float* out = (float*)d_out;

    (void)in_sizes; (void)n_in; (void)out_size;

    cudaFuncSetAttribute(k_out, cudaFuncAttributeMaxDynamicSharedMemorySize,
                         (int)sizeof(OutSmem));
    cudaFuncSetAttribute(k_attn, cudaFuncAttributeMaxDynamicSharedMemorySize,
                         (int)sizeof(AttnSmem));

    k_ln_tri<<<NP / 8, 256>>>(x, ln_w, ln_b, w_tri);
    k_attn<<<dim3(N, H), 256, sizeof(AttnSmem)>>>(mask, wq, wk, wv, wg, bg);
    k_out<<<NP / 128, 256, sizeof(OutSmem)>>>(wo, bo, out);
}